// round 1
// baseline (speedup 1.0000x reference)
#include <cuda_runtime.h>
#include <cuda_bf16.h>
#include <math.h>
#include <stdint.h>

#define B_SZ 2
#define T_SZ 2048
#define HID  2048
#define NH   16
#define NKV  4
#define HD   128

// ---------------- scratch (static device globals; no allocation) ----------------
__device__ float g_q[(size_t)B_SZ * T_SZ * HID];          // [B*T, NH*HD]
__device__ float g_k[(size_t)B_SZ * T_SZ * NKV * HD];     // [B*T, NKV*HD]
__device__ float g_v[(size_t)B_SZ * T_SZ * NKV * HD];     // [B*T, NKV*HD]
__device__ float g_attn[(size_t)B_SZ * T_SZ * HID];       // [B*T, NH*HD]
__device__ float g_cos[T_SZ * 64];
__device__ float g_sin[T_SZ * 64];

// ---------------- RoPE table (double precision -> exact angles) ----------------
__global__ void build_rope_table() {
    int idx = blockIdx.x * blockDim.x + threadIdx.x;
    if (idx >= T_SZ * 64) return;
    int i = idx & 63;
    int t = idx >> 6;
    double inv_freq = pow(10000.0, -(double)i / 64.0);
    double ang = (double)t * inv_freq;
    g_cos[idx] = (float)cos(ang);
    g_sin[idx] = (float)sin(ang);
}

// ---------------- in-place RoPE on [B*T, nheads*128] ----------------
__global__ void rope_kernel(float* __restrict__ buf, int nheads) {
    int idx = blockIdx.x * blockDim.x + threadIdx.x;
    int total = B_SZ * T_SZ * nheads * 64;
    if (idx >= total) return;
    int i  = idx & 63;
    int h  = (idx >> 6) % nheads;
    int bt = idx / (64 * nheads);
    int t  = bt & (T_SZ - 1);
    float c = g_cos[t * 64 + i];
    float s = g_sin[t * 64 + i];
    float* p = buf + (size_t)bt * (nheads * HD) + h * HD + i;
    float x1 = p[0], x2 = p[64];
    p[0]  = x1 * c - x2 * s;
    p[64] = x2 * c + x1 * s;
}

// ---------------- SGEMM: C[M,N] = A[M,K] * B[N,K]^T ----------------
// 64x64 tile, BK=16, 16x16 threads, 4x4 microkernel
__global__ void sgemm_nt(const float* __restrict__ A, const float* __restrict__ Bm,
                         float* __restrict__ C, int M, int N, int K) {
    __shared__ float As[16][68];
    __shared__ float Bs[16][68];
    const int tx = threadIdx.x, ty = threadIdx.y;
    const int tid = ty * 16 + tx;
    const int row0 = blockIdx.y * 64, col0 = blockIdx.x * 64;
    const int lr = tid >> 2;           // 0..63
    const int lk = (tid & 3) << 2;     // 0,4,8,12
    float acc[4][4] = {};
    const float* Aptr = A + (size_t)(row0 + lr) * K + lk;
    const float* Bptr = Bm + (size_t)(col0 + lr) * K + lk;
    for (int k0 = 0; k0 < K; k0 += 16) {
        float4 a4 = *(const float4*)(Aptr + k0);
        float4 b4 = *(const float4*)(Bptr + k0);
        As[lk + 0][lr] = a4.x; As[lk + 1][lr] = a4.y; As[lk + 2][lr] = a4.z; As[lk + 3][lr] = a4.w;
        Bs[lk + 0][lr] = b4.x; Bs[lk + 1][lr] = b4.y; Bs[lk + 2][lr] = b4.z; Bs[lk + 3][lr] = b4.w;
        __syncthreads();
#pragma unroll
        for (int kk = 0; kk < 16; kk++) {
            float4 av = *(const float4*)&As[kk][ty * 4];
            float4 bv = *(const float4*)&Bs[kk][tx * 4];
            float a[4] = {av.x, av.y, av.z, av.w};
            float b[4] = {bv.x, bv.y, bv.z, bv.w};
#pragma unroll
            for (int i = 0; i < 4; i++)
#pragma unroll
                for (int j = 0; j < 4; j++)
                    acc[i][j] += a[i] * b[j];
        }
        __syncthreads();
    }
#pragma unroll
    for (int i = 0; i < 4; i++) {
        float4 o = make_float4(acc[i][0], acc[i][1], acc[i][2], acc[i][3]);
        *(float4*)&C[(size_t)(row0 + ty * 4 + i) * N + col0 + tx * 4] = o;
    }
}

// ---------------- Flash attention (causal, GQA) ----------------
// grid (T/64, NH, B), 256 threads (8 warps). Warp w owns q rows w*8..w*8+7.
// smem: Qs/Ks/Vs 64x132 (pad -> conflict-free LDS128), Ps 64x66.
#define FSTR 132
#define PSTR 66
#define FLASH_SMEM ((3 * 64 * FSTR + 64 * PSTR) * 4)

__global__ void flash_kernel(const float* __restrict__ Qb, const float* __restrict__ Kb,
                             const float* __restrict__ Vb, float* __restrict__ Ob) {
    extern __shared__ float sm[];
    float* Qs = sm;
    float* Ks = sm + 64 * FSTR;
    float* Vs = sm + 2 * 64 * FSTR;
    float* Ps = sm + 3 * 64 * FSTR;
    const int qt = blockIdx.x, h = blockIdx.y, b = blockIdx.z;
    const int kvh = h >> 2;   // NH/NKV = 4 heads per kv head
    const int tid = threadIdx.x;
    const int lane = tid & 31, w = tid >> 5;
    const int q0 = qt * 64;
    const float scale = 0.08838834764831843f;  // 1/sqrt(128)

    // load Q tile
    for (int i = tid; i < 64 * 32; i += 256) {
        int r = i >> 5, dv = (i & 31) << 2;
        *(float4*)&Qs[r * FSTR + dv] =
            *(const float4*)&Qb[((size_t)(b * T_SZ + q0 + r)) * HID + h * HD + dv];
    }
    float acc[8][4];
    float m_r[8], l_r[8];
#pragma unroll
    for (int r = 0; r < 8; r++) {
        m_r[r] = -1e30f; l_r[r] = 0.f;
#pragma unroll
        for (int j = 0; j < 4; j++) acc[r][j] = 0.f;
    }
    __syncthreads();

    for (int kt = 0; kt <= qt; kt++) {
        const int k0 = kt * 64;
        for (int i = tid; i < 64 * 32; i += 256) {
            int r = i >> 5, dv = (i & 31) << 2;
            size_t base = ((size_t)(b * T_SZ + k0 + r)) * (NKV * HD) + kvh * HD + dv;
            *(float4*)&Ks[r * FSTR + dv] = *(const float4*)&Kb[base];
            *(float4*)&Vs[r * FSTR + dv] = *(const float4*)&Vb[base];
        }
        __syncthreads();

        // scores: lane covers cols lane, lane+32 for all 8 rows of its warp
        float s0[8], s1[8];
#pragma unroll
        for (int r = 0; r < 8; r++) { s0[r] = 0.f; s1[r] = 0.f; }
        for (int dv = 0; dv < HD; dv += 4) {
            float4 ka = *(const float4*)&Ks[lane * FSTR + dv];
            float4 kb = *(const float4*)&Ks[(lane + 32) * FSTR + dv];
#pragma unroll
            for (int r = 0; r < 8; r++) {
                float4 qv = *(const float4*)&Qs[(w * 8 + r) * FSTR + dv];
                s0[r] += qv.x * ka.x + qv.y * ka.y + qv.z * ka.z + qv.w * ka.w;
                s1[r] += qv.x * kb.x + qv.y * kb.y + qv.z * kb.z + qv.w * kb.w;
            }
        }
        const bool diag = (kt == qt);
#pragma unroll
        for (int r = 0; r < 8; r++) {
            int grow = q0 + w * 8 + r;
            float v0 = s0[r] * scale, v1 = s1[r] * scale;
            if (diag) {
                if (k0 + lane > grow)      v0 = -1e30f;
                if (k0 + lane + 32 > grow) v1 = -1e30f;
            }
            float mx = fmaxf(v0, v1);
#pragma unroll
            for (int off = 16; off; off >>= 1)
                mx = fmaxf(mx, __shfl_xor_sync(0xffffffffu, mx, off));
            float mnew = fmaxf(m_r[r], mx);
            float p0 = __expf(v0 - mnew), p1 = __expf(v1 - mnew);
            float ps = p0 + p1;
#pragma unroll
            for (int off = 16; off; off >>= 1)
                ps += __shfl_xor_sync(0xffffffffu, ps, off);
            float alpha = __expf(m_r[r] - mnew);
            l_r[r] = l_r[r] * alpha + ps;
            m_r[r] = mnew;
#pragma unroll
            for (int j = 0; j < 4; j++) acc[r][j] *= alpha;
            Ps[(w * 8 + r) * PSTR + lane] = p0;
            Ps[(w * 8 + r) * PSTR + lane + 32] = p1;
        }
        __syncwarp();
        // acc += P @ V : lane owns d = lane*4..lane*4+3
        for (int c = 0; c < 64; c++) {
            float4 vv = *(const float4*)&Vs[c * FSTR + lane * 4];
#pragma unroll
            for (int r = 0; r < 8; r++) {
                float p = Ps[(w * 8 + r) * PSTR + c];
                acc[r][0] += p * vv.x;
                acc[r][1] += p * vv.y;
                acc[r][2] += p * vv.z;
                acc[r][3] += p * vv.w;
            }
        }
        __syncthreads();
    }
#pragma unroll
    for (int r = 0; r < 8; r++) {
        float inv = 1.0f / l_r[r];
        int t = q0 + w * 8 + r;
        float4 o = make_float4(acc[r][0] * inv, acc[r][1] * inv,
                               acc[r][2] * inv, acc[r][3] * inv);
        *(float4*)&Ob[((size_t)(b * T_SZ + t)) * HID + h * HD + lane * 4] = o;
    }
}

// ---------------- launch ----------------
extern "C" void kernel_launch(void* const* d_in, const int* in_sizes, int n_in,
                              void* d_out, int out_size) {
    const float* x  = (const float*)d_in[0];
    // d_in[1] = mask (unused by reference)
    const float* Wq = (const float*)d_in[2];
    const float* Wk = (const float*)d_in[3];
    const float* Wv = (const float*)d_in[4];
    const float* Wo = (const float*)d_in[5];
    float* out = (float*)d_out;

    float *q, *k, *v, *attn;
    cudaGetSymbolAddress((void**)&q, g_q);
    cudaGetSymbolAddress((void**)&k, g_k);
    cudaGetSymbolAddress((void**)&v, g_v);
    cudaGetSymbolAddress((void**)&attn, g_attn);

    const int M = B_SZ * T_SZ;  // 4096
    dim3 blk(16, 16);

    // QKV projections
    sgemm_nt<<<dim3(HID / 64, M / 64), blk>>>(x, Wq, q, M, HID, HID);
    sgemm_nt<<<dim3((NKV * HD) / 64, M / 64), blk>>>(x, Wk, k, M, NKV * HD, HID);
    sgemm_nt<<<dim3((NKV * HD) / 64, M / 64), blk>>>(x, Wv, v, M, NKV * HD, HID);

    // RoPE
    build_rope_table<<<(T_SZ * 64 + 255) / 256, 256>>>();
    rope_kernel<<<(M * NH * 64 + 255) / 256, 256>>>(q, NH);
    rope_kernel<<<(M * NKV * 64 + 255) / 256, 256>>>(k, NKV);

    // attention
    cudaFuncSetAttribute(flash_kernel, cudaFuncAttributeMaxDynamicSharedMemorySize,
                         FLASH_SMEM);
    flash_kernel<<<dim3(T_SZ / 64, NH, B_SZ), 256, FLASH_SMEM>>>(q, k, v, attn);

    // output projection
    sgemm_nt<<<dim3(HID / 64, M / 64), blk>>>(attn, Wo, out, M, HID, HID);
}

// round 7
// speedup vs baseline: 1.3346x; 1.3346x over previous
#include <cuda_runtime.h>
#include <cuda_bf16.h>
#include <math.h>
#include <stdint.h>

#define B_SZ 2
#define T_SZ 2048
#define HID  2048
#define NH   16
#define NKV  4
#define HD   128

// ---------------- scratch ----------------
__device__ float g_q[(size_t)B_SZ * T_SZ * HID];
__device__ float g_k[(size_t)B_SZ * T_SZ * NKV * HD];
__device__ float g_v[(size_t)B_SZ * T_SZ * NKV * HD];
__device__ float g_attn[(size_t)B_SZ * T_SZ * HID];
__device__ float g_cos[T_SZ * 64];
__device__ float g_sin[T_SZ * 64];

// ---------------- RoPE table ----------------
__global__ void build_rope_table() {
    int idx = blockIdx.x * blockDim.x + threadIdx.x;
    if (idx >= T_SZ * 64) return;
    int i = idx & 63;
    int t = idx >> 6;
    double inv_freq = pow(10000.0, -(double)i / 64.0);
    double ang = (double)t * inv_freq;
    g_cos[idx] = (float)cos(ang);
    g_sin[idx] = (float)sin(ang);
}

__global__ void rope_kernel(float* __restrict__ buf, int nheads) {
    int idx = blockIdx.x * blockDim.x + threadIdx.x;
    int total = B_SZ * T_SZ * nheads * 64;
    if (idx >= total) return;
    int i  = idx & 63;
    int h  = (idx >> 6) % nheads;
    int bt = idx / (64 * nheads);
    int t  = bt & (T_SZ - 1);
    float c = g_cos[t * 64 + i];
    float s = g_sin[t * 64 + i];
    float* p = buf + (size_t)bt * (nheads * HD) + h * HD + i;
    float x1 = p[0], x2 = p[64];
    p[0]  = x1 * c - x2 * s;
    p[64] = x2 * c + x1 * s;
}

// ============ mma.sync tf32 GEMM: C[M,N] = A[M,K] * B[N,K]^T ============
// Tile 128x128, BK=32, 256 threads = 8 warps in a 2(m) x 4(n) grid.
// Each warp: 64x32 output = 4x4 grid of m16n8k8 tf32 mma fragments.

#define BM 128
#define BN 128
#define BKC 32
#define GSTR 33   // smem row stride (floats), padded

__device__ __forceinline__ uint32_t f2tf32(float f) {
    uint32_t u; asm("cvt.rna.tf32.f32 %0, %1;" : "=r"(u) : "f"(f)); return u;
}
__device__ __forceinline__ void mma_tf32(float* d, const uint32_t* a, const uint32_t* b) {
    asm volatile(
        "mma.sync.aligned.m16n8k8.row.col.f32.tf32.tf32.f32 "
        "{%0,%1,%2,%3}, {%4,%5,%6,%7}, {%8,%9}, {%0,%1,%2,%3};\n"
        : "+f"(d[0]), "+f"(d[1]), "+f"(d[2]), "+f"(d[3])
        : "r"(a[0]), "r"(a[1]), "r"(a[2]), "r"(a[3]), "r"(b[0]), "r"(b[1]));
}

__global__ void __launch_bounds__(256)
gemm_mma_tf32(const float* __restrict__ A, const float* __restrict__ Bm,
              float* __restrict__ C, int N, int K) {
    __shared__ float As[BM * GSTR];
    __shared__ float Bs[BN * GSTR];
    const int tid  = threadIdx.x;
    const int lane = tid & 31, w = tid >> 5;
    const int wm = w & 1, wn = w >> 1;         // warp position: 2 x 4
    const int g = lane >> 2, tig = lane & 3;   // groupID, thread-in-group
    const int row0 = blockIdx.y * BM, col0 = blockIdx.x * BN;

    float acc[4][4][4];
#pragma unroll
    for (int mt = 0; mt < 4; mt++)
#pragma unroll
        for (int nt = 0; nt < 4; nt++)
#pragma unroll
            for (int j = 0; j < 4; j++) acc[mt][nt][j] = 0.f;

    for (int k0 = 0; k0 < K; k0 += BKC) {
        // ---- load A,B tiles (128x32 each) to smem, converting to tf32 ----
#pragma unroll
        for (int j = 0; j < 4; j++) {
            int s = tid + j * 256;            // 1024 float4 slots per tile
            int r = s >> 3, c4 = (s & 7) << 2;
            float4 a = *(const float4*)(A + (size_t)(row0 + r) * K + k0 + c4);
            As[r * GSTR + c4 + 0] = __uint_as_float(f2tf32(a.x));
            As[r * GSTR + c4 + 1] = __uint_as_float(f2tf32(a.y));
            As[r * GSTR + c4 + 2] = __uint_as_float(f2tf32(a.z));
            As[r * GSTR + c4 + 3] = __uint_as_float(f2tf32(a.w));
            float4 b = *(const float4*)(Bm + (size_t)(col0 + r) * K + k0 + c4);
            Bs[r * GSTR + c4 + 0] = __uint_as_float(f2tf32(b.x));
            Bs[r * GSTR + c4 + 1] = __uint_as_float(f2tf32(b.y));
            Bs[r * GSTR + c4 + 2] = __uint_as_float(f2tf32(b.z));
            Bs[r * GSTR + c4 + 3] = __uint_as_float(f2tf32(b.w));
        }
        __syncthreads();

        // ---- 4 k-steps of 8 ----
#pragma unroll
        for (int ks = 0; ks < 4; ks++) {
            const int kb = ks * 8;
            uint32_t afr[4][4];
#pragma unroll
            for (int mt = 0; mt < 4; mt++) {
                int r = wm * 64 + mt * 16 + g;
                afr[mt][0] = __float_as_uint(As[r * GSTR + kb + tig]);
                afr[mt][1] = __float_as_uint(As[(r + 8) * GSTR + kb + tig]);
                afr[mt][2] = __float_as_uint(As[r * GSTR + kb + tig + 4]);
                afr[mt][3] = __float_as_uint(As[(r + 8) * GSTR + kb + tig + 4]);
            }
            uint32_t bfr[4][2];
#pragma unroll
            for (int nt = 0; nt < 4; nt++) {
                int c = wn * 32 + nt * 8 + g;
                bfr[nt][0] = __float_as_uint(Bs[c * GSTR + kb + tig]);
                bfr[nt][1] = __float_as_uint(Bs[c * GSTR + kb + tig + 4]);
            }
#pragma unroll
            for (int mt = 0; mt < 4; mt++)
#pragma unroll
                for (int nt = 0; nt < 4; nt++)
                    mma_tf32(acc[mt][nt], afr[mt], bfr[nt]);
        }
        __syncthreads();
    }

    // ---- epilogue: fragment layout c0,c1 @ (g, 2*tig), c2,c3 @ (g+8, 2*tig) ----
#pragma unroll
    for (int mt = 0; mt < 4; mt++) {
        int r = row0 + wm * 64 + mt * 16 + g;
#pragma unroll
        for (int nt = 0; nt < 4; nt++) {
            int c = col0 + wn * 32 + nt * 8 + tig * 2;
            *(float2*)(C + (size_t)r * N + c)       = make_float2(acc[mt][nt][0], acc[mt][nt][1]);
            *(float2*)(C + (size_t)(r + 8) * N + c) = make_float2(acc[mt][nt][2], acc[mt][nt][3]);
        }
    }
}

// ---------------- Flash attention (causal, GQA) — fp32, round-1 proven ----------------
#define FSTR 132
#define PSTR 66
#define FLASH_SMEM ((3 * 64 * FSTR + 64 * PSTR) * 4)

__global__ void flash_kernel(const float* __restrict__ Qb, const float* __restrict__ Kb,
                             const float* __restrict__ Vb, float* __restrict__ Ob) {
    extern __shared__ float sm[];
    float* Qs = sm;
    float* Ks = sm + 64 * FSTR;
    float* Vs = sm + 2 * 64 * FSTR;
    float* Ps = sm + 3 * 64 * FSTR;
    const int qt = blockIdx.x, h = blockIdx.y, b = blockIdx.z;
    const int kvh = h >> 2;
    const int tid = threadIdx.x;
    const int lane = tid & 31, w = tid >> 5;
    const int q0 = qt * 64;
    const float scale = 0.08838834764831843f;

    for (int i = tid; i < 64 * 32; i += 256) {
        int r = i >> 5, dv = (i & 31) << 2;
        *(float4*)&Qs[r * FSTR + dv] =
            *(const float4*)&Qb[((size_t)(b * T_SZ + q0 + r)) * HID + h * HD + dv];
    }
    float acc[8][4];
    float m_r[8], l_r[8];
#pragma unroll
    for (int r = 0; r < 8; r++) {
        m_r[r] = -1e30f; l_r[r] = 0.f;
#pragma unroll
        for (int j = 0; j < 4; j++) acc[r][j] = 0.f;
    }
    __syncthreads();

    for (int kt = 0; kt <= qt; kt++) {
        const int k0 = kt * 64;
        for (int i = tid; i < 64 * 32; i += 256) {
            int r = i >> 5, dv = (i & 31) << 2;
            size_t base = ((size_t)(b * T_SZ + k0 + r)) * (NKV * HD) + kvh * HD + dv;
            *(float4*)&Ks[r * FSTR + dv] = *(const float4*)&Kb[base];
            *(float4*)&Vs[r * FSTR + dv] = *(const float4*)&Vb[base];
        }
        __syncthreads();

        float s0[8], s1[8];
#pragma unroll
        for (int r = 0; r < 8; r++) { s0[r] = 0.f; s1[r] = 0.f; }
        for (int dv = 0; dv < HD; dv += 4) {
            float4 ka = *(const float4*)&Ks[lane * FSTR + dv];
            float4 kb = *(const float4*)&Ks[(lane + 32) * FSTR + dv];
#pragma unroll
            for (int r = 0; r < 8; r++) {
                float4 qv = *(const float4*)&Qs[(w * 8 + r) * FSTR + dv];
                s0[r] += qv.x * ka.x + qv.y * ka.y + qv.z * ka.z + qv.w * ka.w;
                s1[r] += qv.x * kb.x + qv.y * kb.y + qv.z * kb.z + qv.w * kb.w;
            }
        }
        const bool diag = (kt == qt);
#pragma unroll
        for (int r = 0; r < 8; r++) {
            int grow = q0 + w * 8 + r;
            float v0 = s0[r] * scale, v1 = s1[r] * scale;
            if (diag) {
                if (k0 + lane > grow)      v0 = -1e30f;
                if (k0 + lane + 32 > grow) v1 = -1e30f;
            }
            float mx = fmaxf(v0, v1);
#pragma unroll
            for (int off = 16; off; off >>= 1)
                mx = fmaxf(mx, __shfl_xor_sync(0xffffffffu, mx, off));
            float mnew = fmaxf(m_r[r], mx);
            float p0 = __expf(v0 - mnew), p1 = __expf(v1 - mnew);
            float ps = p0 + p1;
#pragma unroll
            for (int off = 16; off; off >>= 1)
                ps += __shfl_xor_sync(0xffffffffu, ps, off);
            float alpha = __expf(m_r[r] - mnew);
            l_r[r] = l_r[r] * alpha + ps;
            m_r[r] = mnew;
#pragma unroll
            for (int j = 0; j < 4; j++) acc[r][j] *= alpha;
            Ps[(w * 8 + r) * PSTR + lane] = p0;
            Ps[(w * 8 + r) * PSTR + lane + 32] = p1;
        }
        __syncwarp();
        for (int c = 0; c < 64; c++) {
            float4 vv = *(const float4*)&Vs[c * FSTR + lane * 4];
#pragma unroll
            for (int r = 0; r < 8; r++) {
                float p = Ps[(w * 8 + r) * PSTR + c];
                acc[r][0] += p * vv.x;
                acc[r][1] += p * vv.y;
                acc[r][2] += p * vv.z;
                acc[r][3] += p * vv.w;
            }
        }
        __syncthreads();
    }
#pragma unroll
    for (int r = 0; r < 8; r++) {
        float inv = 1.0f / l_r[r];
        int t = q0 + w * 8 + r;
        float4 o = make_float4(acc[r][0] * inv, acc[r][1] * inv,
                               acc[r][2] * inv, acc[r][3] * inv);
        *(float4*)&Ob[((size_t)(b * T_SZ + t)) * HID + h * HD + lane * 4] = o;
    }
}

// ---------------- launch ----------------
extern "C" void kernel_launch(void* const* d_in, const int* in_sizes, int n_in,
                              void* d_out, int out_size) {
    const float* x  = (const float*)d_in[0];
    const float* Wq = (const float*)d_in[2];
    const float* Wk = (const float*)d_in[3];
    const float* Wv = (const float*)d_in[4];
    const float* Wo = (const float*)d_in[5];
    float* out = (float*)d_out;

    float *q, *k, *v, *attn;
    cudaGetSymbolAddress((void**)&q, g_q);
    cudaGetSymbolAddress((void**)&k, g_k);
    cudaGetSymbolAddress((void**)&v, g_v);
    cudaGetSymbolAddress((void**)&attn, g_attn);

    const int M = B_SZ * T_SZ;  // 4096

    cudaFuncSetAttribute(flash_kernel, cudaFuncAttributeMaxDynamicSharedMemorySize, FLASH_SMEM);

    // QKV projections (mma.sync tf32)
    gemm_mma_tf32<<<dim3(HID / BN, M / BM), 256>>>(x, Wq, q, HID, HID);
    gemm_mma_tf32<<<dim3((NKV * HD) / BN, M / BM), 256>>>(x, Wk, k, NKV * HD, HID);
    gemm_mma_tf32<<<dim3((NKV * HD) / BN, M / BM), 256>>>(x, Wv, v, NKV * HD, HID);

    // RoPE
    build_rope_table<<<(T_SZ * 64 + 255) / 256, 256>>>();
    rope_kernel<<<(M * NH * 64 + 255) / 256, 256>>>(q, NH);
    rope_kernel<<<(M * NKV * 64 + 255) / 256, 256>>>(k, NKV);

    // attention (fp32 flash)
    flash_kernel<<<dim3(T_SZ / 64, NH, B_SZ), 256, FLASH_SMEM>>>(q, k, v, attn);

    // output projection (mma.sync tf32)
    gemm_mma_tf32<<<dim3(HID / BN, M / BM), 256>>>(attn, Wo, out, HID, HID);
}

// round 8
// speedup vs baseline: 2.0689x; 1.5501x over previous
#include <cuda_runtime.h>
#include <cuda_bf16.h>
#include <math.h>
#include <stdint.h>

#define B_SZ 2
#define T_SZ 2048
#define HID  2048
#define NH   16
#define NKV  4
#define HD   128

// ---------------- scratch ----------------
__device__ float g_q[(size_t)B_SZ * T_SZ * HID];
__device__ float g_k[(size_t)B_SZ * T_SZ * NKV * HD];
__device__ float g_v[(size_t)B_SZ * T_SZ * NKV * HD];
__device__ float g_attn[(size_t)B_SZ * T_SZ * HID];
__device__ float g_cos[T_SZ * 64];
__device__ float g_sin[T_SZ * 64];

// ---------------- RoPE table ----------------
__global__ void build_rope_table() {
    int idx = blockIdx.x * blockDim.x + threadIdx.x;
    if (idx >= T_SZ * 64) return;
    int i = idx & 63;
    int t = idx >> 6;
    double inv_freq = pow(10000.0, -(double)i / 64.0);
    double ang = (double)t * inv_freq;
    g_cos[idx] = (float)cos(ang);
    g_sin[idx] = (float)sin(ang);
}

__global__ void rope_kernel(float* __restrict__ buf, int nheads) {
    int idx = blockIdx.x * blockDim.x + threadIdx.x;
    int total = B_SZ * T_SZ * nheads * 64;
    if (idx >= total) return;
    int i  = idx & 63;
    int h  = (idx >> 6) % nheads;
    int bt = idx / (64 * nheads);
    int t  = bt & (T_SZ - 1);
    float c = g_cos[t * 64 + i];
    float s = g_sin[t * 64 + i];
    float* p = buf + (size_t)bt * (nheads * HD) + h * HD + i;
    float x1 = p[0], x2 = p[64];
    p[0]  = x1 * c - x2 * s;
    p[64] = x2 * c + x1 * s;
}

// ---------------- common mma helpers ----------------
__device__ __forceinline__ uint32_t f2tf32(float f) {
    uint32_t u; asm("cvt.rna.tf32.f32 %0, %1;" : "=r"(u) : "f"(f)); return u;
}
__device__ __forceinline__ void mma_tf32(float* d, const uint32_t* a, const uint32_t* b) {
    asm volatile(
        "mma.sync.aligned.m16n8k8.row.col.f32.tf32.tf32.f32 "
        "{%0,%1,%2,%3}, {%4,%5,%6,%7}, {%8,%9}, {%0,%1,%2,%3};\n"
        : "+f"(d[0]), "+f"(d[1]), "+f"(d[2]), "+f"(d[3])
        : "r"(a[0]), "r"(a[1]), "r"(a[2]), "r"(a[3]), "r"(b[0]), "r"(b[1]));
}
__device__ __forceinline__ float ex2(float x) {
    float y; asm("ex2.approx.ftz.f32 %0, %1;" : "=f"(y) : "f"(x)); return y;
}

// ============ mma.sync tf32 GEMM: C[M,N] = A[M,K] * B[N,K]^T (round-7 proven) ============
#define BM 128
#define BN 128
#define BKC 32
#define GSTR 33

__global__ void __launch_bounds__(256)
gemm_mma_tf32(const float* __restrict__ A, const float* __restrict__ Bm,
              float* __restrict__ C, int N, int K) {
    __shared__ float As[BM * GSTR];
    __shared__ float Bs[BN * GSTR];
    const int tid  = threadIdx.x;
    const int lane = tid & 31, w = tid >> 5;
    const int wm = w & 1, wn = w >> 1;
    const int g = lane >> 2, tig = lane & 3;
    const int row0 = blockIdx.y * BM, col0 = blockIdx.x * BN;

    float acc[4][4][4];
#pragma unroll
    for (int mt = 0; mt < 4; mt++)
#pragma unroll
        for (int nt = 0; nt < 4; nt++)
#pragma unroll
            for (int j = 0; j < 4; j++) acc[mt][nt][j] = 0.f;

    for (int k0 = 0; k0 < K; k0 += BKC) {
#pragma unroll
        for (int j = 0; j < 4; j++) {
            int s = tid + j * 256;
            int r = s >> 3, c4 = (s & 7) << 2;
            float4 a = *(const float4*)(A + (size_t)(row0 + r) * K + k0 + c4);
            As[r * GSTR + c4 + 0] = __uint_as_float(f2tf32(a.x));
            As[r * GSTR + c4 + 1] = __uint_as_float(f2tf32(a.y));
            As[r * GSTR + c4 + 2] = __uint_as_float(f2tf32(a.z));
            As[r * GSTR + c4 + 3] = __uint_as_float(f2tf32(a.w));
            float4 b = *(const float4*)(Bm + (size_t)(col0 + r) * K + k0 + c4);
            Bs[r * GSTR + c4 + 0] = __uint_as_float(f2tf32(b.x));
            Bs[r * GSTR + c4 + 1] = __uint_as_float(f2tf32(b.y));
            Bs[r * GSTR + c4 + 2] = __uint_as_float(f2tf32(b.z));
            Bs[r * GSTR + c4 + 3] = __uint_as_float(f2tf32(b.w));
        }
        __syncthreads();

#pragma unroll
        for (int ks = 0; ks < 4; ks++) {
            const int kb = ks * 8;
            uint32_t afr[4][4];
#pragma unroll
            for (int mt = 0; mt < 4; mt++) {
                int r = wm * 64 + mt * 16 + g;
                afr[mt][0] = __float_as_uint(As[r * GSTR + kb + tig]);
                afr[mt][1] = __float_as_uint(As[(r + 8) * GSTR + kb + tig]);
                afr[mt][2] = __float_as_uint(As[r * GSTR + kb + tig + 4]);
                afr[mt][3] = __float_as_uint(As[(r + 8) * GSTR + kb + tig + 4]);
            }
            uint32_t bfr[4][2];
#pragma unroll
            for (int nt = 0; nt < 4; nt++) {
                int c = wn * 32 + nt * 8 + g;
                bfr[nt][0] = __float_as_uint(Bs[c * GSTR + kb + tig]);
                bfr[nt][1] = __float_as_uint(Bs[c * GSTR + kb + tig + 4]);
            }
#pragma unroll
            for (int mt = 0; mt < 4; mt++)
#pragma unroll
                for (int nt = 0; nt < 4; nt++)
                    mma_tf32(acc[mt][nt], afr[mt], bfr[nt]);
        }
        __syncthreads();
    }

#pragma unroll
    for (int mt = 0; mt < 4; mt++) {
        int r = row0 + wm * 64 + mt * 16 + g;
#pragma unroll
        for (int nt = 0; nt < 4; nt++) {
            int c = col0 + wn * 32 + nt * 8 + tig * 2;
            *(float2*)(C + (size_t)r * N + c)       = make_float2(acc[mt][nt][0], acc[mt][nt][1]);
            *(float2*)(C + (size_t)(r + 8) * N + c) = make_float2(acc[mt][nt][2], acc[mt][nt][3]);
        }
    }
}

// ============ tensor-core flash attention (causal, GQA, tf32 mma) ============
// Block: 128 q-rows, grid (T/128, NH, B), 256 threads = 8 warps, warp owns 16 rows.
#define FQ  128
#define FKT 64
#define QS  132    // Q/K/V smem stride (floats): frag banks = 4g+tig, conflict-free
#define PS2 68     // P smem stride
#define FLASH2_SMEM ((FQ * QS + 2 * FKT * QS + FQ * PS2) * 4)

__global__ void __launch_bounds__(256)
flash_mma(const float* __restrict__ Qb, const float* __restrict__ Kb,
          const float* __restrict__ Vb, float* __restrict__ Ob) {
    extern __shared__ float sm[];
    float* Qs = sm;                    // [128][132]
    float* Ks = sm + FQ * QS;          // [64][132]
    float* Vs = Ks + FKT * QS;         // [64][132]
    float* Ps = Vs + FKT * QS;         // [128][68]
    const int qt = blockIdx.x, h = blockIdx.y, b = blockIdx.z;
    const int kvh = h >> 2;
    const int tid = threadIdx.x, lane = tid & 31, w = tid >> 5;
    const int g = lane >> 2, tig = lane & 3;
    const int q0 = qt * FQ;
    // fold softmax scale and log2(e) into Q so softmax runs in base 2
    const float qscale = 0.08838834764831843f * 1.4426950408889634f;

    // load Q tile (pre-scaled, tf32-rounded)
    for (int i = tid; i < FQ * 32; i += 256) {
        int r = i >> 5, c4 = (i & 31) << 2;
        float4 qv = *(const float4*)&Qb[((size_t)(b * T_SZ + q0 + r)) * HID + h * HD + c4];
        Qs[r * QS + c4 + 0] = __uint_as_float(f2tf32(qv.x * qscale));
        Qs[r * QS + c4 + 1] = __uint_as_float(f2tf32(qv.y * qscale));
        Qs[r * QS + c4 + 2] = __uint_as_float(f2tf32(qv.z * qscale));
        Qs[r * QS + c4 + 3] = __uint_as_float(f2tf32(qv.w * qscale));
    }

    float O[16][4];
#pragma unroll
    for (int nt = 0; nt < 16; nt++)
#pragma unroll
        for (int j = 0; j < 4; j++) O[nt][j] = 0.f;
    float m0 = -1e30f, m1 = -1e30f, l0 = 0.f, l1 = 0.f;

    const int row_g = q0 + w * 16 + g;   // this thread's first q row
    const int ntile = 2 * qt + 2;

    for (int kt = 0; kt < ntile; kt++) {
        const int k0 = kt * FKT;
        // load K,V tiles (tf32-rounded)
        for (int i = tid; i < FKT * 32; i += 256) {
            int r = i >> 5, c4 = (i & 31) << 2;
            size_t base = ((size_t)(b * T_SZ + k0 + r)) * (NKV * HD) + kvh * HD + c4;
            float4 k4 = *(const float4*)&Kb[base];
            Ks[r * QS + c4 + 0] = __uint_as_float(f2tf32(k4.x));
            Ks[r * QS + c4 + 1] = __uint_as_float(f2tf32(k4.y));
            Ks[r * QS + c4 + 2] = __uint_as_float(f2tf32(k4.z));
            Ks[r * QS + c4 + 3] = __uint_as_float(f2tf32(k4.w));
            float4 v4 = *(const float4*)&Vb[base];
            Vs[r * QS + c4 + 0] = __uint_as_float(f2tf32(v4.x));
            Vs[r * QS + c4 + 1] = __uint_as_float(f2tf32(v4.y));
            Vs[r * QS + c4 + 2] = __uint_as_float(f2tf32(v4.z));
            Vs[r * QS + c4 + 3] = __uint_as_float(f2tf32(v4.w));
        }
        __syncthreads();

        // ---- S = Q K^T : 8 n-tiles x 16 k-steps ----
        float sfr[8][4];
#pragma unroll
        for (int nt = 0; nt < 8; nt++)
#pragma unroll
            for (int j = 0; j < 4; j++) sfr[nt][j] = 0.f;
#pragma unroll
        for (int ks = 0; ks < 16; ks++) {
            const int kb = ks * 8;
            uint32_t a[4];
            int r = w * 16 + g;
            a[0] = __float_as_uint(Qs[r * QS + kb + tig]);
            a[1] = __float_as_uint(Qs[(r + 8) * QS + kb + tig]);
            a[2] = __float_as_uint(Qs[r * QS + kb + tig + 4]);
            a[3] = __float_as_uint(Qs[(r + 8) * QS + kb + tig + 4]);
#pragma unroll
            for (int nt = 0; nt < 8; nt++) {
                uint32_t bb[2];
                bb[0] = __float_as_uint(Ks[(nt * 8 + g) * QS + kb + tig]);
                bb[1] = __float_as_uint(Ks[(nt * 8 + g) * QS + kb + tig + 4]);
                mma_tf32(sfr[nt], a, bb);
            }
        }

        // ---- causal mask (only near the diagonal) ----
        if (k0 + FKT - 1 > q0 + w * 16) {
#pragma unroll
            for (int nt = 0; nt < 8; nt++) {
                int c = k0 + nt * 8 + 2 * tig;
                if (c     > row_g)     sfr[nt][0] = -1e30f;
                if (c + 1 > row_g)     sfr[nt][1] = -1e30f;
                if (c     > row_g + 8) sfr[nt][2] = -1e30f;
                if (c + 1 > row_g + 8) sfr[nt][3] = -1e30f;
            }
        }

        // ---- online softmax (base 2) ----
        float mx0 = -1e30f, mx1 = -1e30f;
#pragma unroll
        for (int nt = 0; nt < 8; nt++) {
            mx0 = fmaxf(mx0, fmaxf(sfr[nt][0], sfr[nt][1]));
            mx1 = fmaxf(mx1, fmaxf(sfr[nt][2], sfr[nt][3]));
        }
        mx0 = fmaxf(mx0, __shfl_xor_sync(0xffffffffu, mx0, 1));
        mx0 = fmaxf(mx0, __shfl_xor_sync(0xffffffffu, mx0, 2));
        mx1 = fmaxf(mx1, __shfl_xor_sync(0xffffffffu, mx1, 1));
        mx1 = fmaxf(mx1, __shfl_xor_sync(0xffffffffu, mx1, 2));
        float mn0 = fmaxf(m0, mx0), mn1 = fmaxf(m1, mx1);
        float al0 = ex2(m0 - mn0), al1 = ex2(m1 - mn1);
        m0 = mn0; m1 = mn1;

        float ps0 = 0.f, ps1 = 0.f;
        const int pr = (w * 16 + g) * PS2;
#pragma unroll
        for (int nt = 0; nt < 8; nt++) {
            float p0 = ex2(sfr[nt][0] - mn0);
            float p1 = ex2(sfr[nt][1] - mn0);
            float p2 = ex2(sfr[nt][2] - mn1);
            float p3 = ex2(sfr[nt][3] - mn1);
            ps0 += p0 + p1;
            ps1 += p2 + p3;
            int c = nt * 8 + 2 * tig;
            *(float2*)&Ps[pr + c] =
                make_float2(__uint_as_float(f2tf32(p0)), __uint_as_float(f2tf32(p1)));
            *(float2*)&Ps[pr + 8 * PS2 + c] =
                make_float2(__uint_as_float(f2tf32(p2)), __uint_as_float(f2tf32(p3)));
        }
        ps0 += __shfl_xor_sync(0xffffffffu, ps0, 1);
        ps0 += __shfl_xor_sync(0xffffffffu, ps0, 2);
        ps1 += __shfl_xor_sync(0xffffffffu, ps1, 1);
        ps1 += __shfl_xor_sync(0xffffffffu, ps1, 2);
        l0 = l0 * al0 + ps0;
        l1 = l1 * al1 + ps1;
#pragma unroll
        for (int nt = 0; nt < 16; nt++) {
            O[nt][0] *= al0; O[nt][1] *= al0;
            O[nt][2] *= al1; O[nt][3] *= al1;
        }
        __syncwarp();   // P rows are warp-private: write->read within warp only

        // ---- O += P V : 16 n-tiles x 8 k-steps ----
#pragma unroll
        for (int ks = 0; ks < 8; ks++) {
            const int kb = ks * 8;
            uint32_t a[4];
            int r = w * 16 + g;
            a[0] = __float_as_uint(Ps[r * PS2 + kb + tig]);
            a[1] = __float_as_uint(Ps[(r + 8) * PS2 + kb + tig]);
            a[2] = __float_as_uint(Ps[r * PS2 + kb + tig + 4]);
            a[3] = __float_as_uint(Ps[(r + 8) * PS2 + kb + tig + 4]);
#pragma unroll
            for (int nt = 0; nt < 16; nt++) {
                uint32_t bb[2];
                bb[0] = __float_as_uint(Vs[(kb + tig) * QS + nt * 8 + g]);
                bb[1] = __float_as_uint(Vs[(kb + tig + 4) * QS + nt * 8 + g]);
                mma_tf32(O[nt], a, bb);
            }
        }
        __syncthreads();   // protect K/V before next tile overwrites
    }

    // ---- epilogue ----
    float inv0 = 1.f / l0, inv1 = 1.f / l1;
    size_t r0 = (size_t)(b * T_SZ + row_g) * HID + h * HD;
    size_t r1 = (size_t)(b * T_SZ + row_g + 8) * HID + h * HD;
#pragma unroll
    for (int nt = 0; nt < 16; nt++) {
        int c = nt * 8 + 2 * tig;
        *(float2*)&Ob[r0 + c] = make_float2(O[nt][0] * inv0, O[nt][1] * inv0);
        *(float2*)&Ob[r1 + c] = make_float2(O[nt][2] * inv1, O[nt][3] * inv1);
    }
}

// ---------------- launch ----------------
extern "C" void kernel_launch(void* const* d_in, const int* in_sizes, int n_in,
                              void* d_out, int out_size) {
    const float* x  = (const float*)d_in[0];
    const float* Wq = (const float*)d_in[2];
    const float* Wk = (const float*)d_in[3];
    const float* Wv = (const float*)d_in[4];
    const float* Wo = (const float*)d_in[5];
    float* out = (float*)d_out;

    float *q, *k, *v, *attn;
    cudaGetSymbolAddress((void**)&q, g_q);
    cudaGetSymbolAddress((void**)&k, g_k);
    cudaGetSymbolAddress((void**)&v, g_v);
    cudaGetSymbolAddress((void**)&attn, g_attn);

    const int M = B_SZ * T_SZ;  // 4096

    cudaFuncSetAttribute(flash_mma, cudaFuncAttributeMaxDynamicSharedMemorySize, FLASH2_SMEM);

    // QKV projections (mma.sync tf32)
    gemm_mma_tf32<<<dim3(HID / BN, M / BM), 256>>>(x, Wq, q, HID, HID);
    gemm_mma_tf32<<<dim3((NKV * HD) / BN, M / BM), 256>>>(x, Wk, k, NKV * HD, HID);
    gemm_mma_tf32<<<dim3((NKV * HD) / BN, M / BM), 256>>>(x, Wv, v, NKV * HD, HID);

    // RoPE
    build_rope_table<<<(T_SZ * 64 + 255) / 256, 256>>>();
    rope_kernel<<<(M * NH * 64 + 255) / 256, 256>>>(q, NH);
    rope_kernel<<<(M * NKV * 64 + 255) / 256, 256>>>(k, NKV);

    // attention (tensor-core flash, tf32)
    flash_mma<<<dim3(T_SZ / FQ, NH, B_SZ), 256, FLASH2_SMEM>>>(q, k, v, attn);

    // output projection (mma.sync tf32)
    gemm_mma_tf32<<<dim3(HID / BN, M / BM), 256>>>(attn, Wo, out, HID, HID);
}

// round 9
// speedup vs baseline: 3.2343x; 1.5633x over previous
#include <cuda_runtime.h>
#include <cuda_bf16.h>
#include <math.h>
#include <stdint.h>

#define B_SZ 2
#define T_SZ 2048
#define HID  2048
#define NH   16
#define NKV  4
#define HD   128

// ---------------- scratch ----------------
__device__ float g_q[(size_t)B_SZ * T_SZ * HID];
__device__ float g_kv[(size_t)B_SZ * T_SZ * 1024];        // k: cols 0-511, v: 512-1023
__device__ float g_attn[(size_t)B_SZ * T_SZ * HID];
__device__ float g_xt[(size_t)B_SZ * T_SZ * HID];         // tf32-rounded copies
__device__ float g_attn_t[(size_t)B_SZ * T_SZ * HID];
__device__ float g_wq_t[(size_t)HID * HID];
__device__ float g_wkv_t[(size_t)1024 * HID];
__device__ float g_wo_t[(size_t)HID * HID];
__device__ float g_cos[T_SZ * 64];
__device__ float g_sin[T_SZ * 64];

// ---------------- helpers ----------------
__device__ __forceinline__ uint32_t f2tf32(float f) {
    uint32_t u; asm("cvt.rna.tf32.f32 %0, %1;" : "=r"(u) : "f"(f)); return u;
}
__device__ __forceinline__ void mma_tf32(float* d, const uint32_t* a, const uint32_t* b) {
    asm volatile(
        "mma.sync.aligned.m16n8k8.row.col.f32.tf32.tf32.f32 "
        "{%0,%1,%2,%3}, {%4,%5,%6,%7}, {%8,%9}, {%0,%1,%2,%3};\n"
        : "+f"(d[0]), "+f"(d[1]), "+f"(d[2]), "+f"(d[3])
        : "r"(a[0]), "r"(a[1]), "r"(a[2]), "r"(a[3]), "r"(b[0]), "r"(b[1]));
}
__device__ __forceinline__ float ex2(float x) {
    float y; asm("ex2.approx.ftz.f32 %0, %1;" : "=f"(y) : "f"(x)); return y;
}
__device__ __forceinline__ uint32_t smem_u32(const void* p) {
    uint32_t a;
    asm("{ .reg .u64 t; cvta.to.shared.u64 t, %1; cvt.u32.u64 %0, t; }" : "=r"(a) : "l"(p));
    return a;
}
__device__ __forceinline__ void cpasync16(uint32_t dst, const void* src) {
    asm volatile("cp.async.cg.shared.global [%0], [%1], 16;" :: "r"(dst), "l"(src));
}

// ---------------- tf32 rounding prepass ----------------
__global__ void conv_tf32(const float4* __restrict__ in, float4* __restrict__ out, int n4) {
    int i = blockIdx.x * blockDim.x + threadIdx.x;
    if (i >= n4) return;
    float4 v = in[i];
    out[i] = make_float4(__uint_as_float(f2tf32(v.x)), __uint_as_float(f2tf32(v.y)),
                         __uint_as_float(f2tf32(v.z)), __uint_as_float(f2tf32(v.w)));
}

// ---------------- RoPE ----------------
__global__ void build_rope_table() {
    int idx = blockIdx.x * blockDim.x + threadIdx.x;
    if (idx >= T_SZ * 64) return;
    int i = idx & 63;
    int t = idx >> 6;
    double inv_freq = pow(10000.0, -(double)i / 64.0);
    double ang = (double)t * inv_freq;
    g_cos[idx] = (float)cos(ang);
    g_sin[idx] = (float)sin(ang);
}

__global__ void rope_kernel(float* __restrict__ buf, int nheads, int rowstr) {
    int idx = blockIdx.x * blockDim.x + threadIdx.x;
    int total = B_SZ * T_SZ * nheads * 64;
    if (idx >= total) return;
    int i  = idx & 63;
    int h  = (idx >> 6) % nheads;
    int bt = idx / (64 * nheads);
    int t  = bt & (T_SZ - 1);
    float c = g_cos[t * 64 + i];
    float s = g_sin[t * 64 + i];
    float* p = buf + (size_t)bt * rowstr + h * HD + i;
    float x1 = p[0], x2 = p[64];
    p[0]  = x1 * c - x2 * s;
    p[64] = x2 * c + x1 * s;
}

// ============ cp.async pipelined tf32 GEMM: C[M,N] = A[M,K]*B[N,K]^T ============
// Inputs pre-rounded to tf32. Tile 128x128, BK=32, 2-stage cp.async double buffer.
#define GS 36                                  // smem row stride (floats), 16B-aligned
#define STAGE_FLOATS (2 * 128 * GS)            // A+B per stage = 9216 floats
#define GEMM_SMEM (2 * STAGE_FLOATS * 4)       // 73728 bytes

__global__ void __launch_bounds__(256)
gemm_pipe(const float* __restrict__ A, const float* __restrict__ Bm,
          float* __restrict__ C, int N, int K) {
    extern __shared__ float sm[];
    const uint32_t sbase = smem_u32(sm);
    const int tid  = threadIdx.x;
    const int lane = tid & 31, w = tid >> 5;
    const int wm = w & 1, wn = w >> 1;
    const int g = lane >> 2, tig = lane & 3;
    const int row0 = blockIdx.y * 128, col0 = blockIdx.x * 128;
    const int nchunk = K / 32;

    float acc[4][4][4];
#pragma unroll
    for (int mt = 0; mt < 4; mt++)
#pragma unroll
        for (int nt = 0; nt < 4; nt++)
#pragma unroll
            for (int j = 0; j < 4; j++) acc[mt][nt][j] = 0.f;

    // per-thread copy slots: 4 x (A 16B + B 16B)
    auto issue = [&](int ci, int st) {
        uint32_t abuf = sbase + (uint32_t)st * STAGE_FLOATS * 4;
        uint32_t bbuf = abuf + 128 * GS * 4;
#pragma unroll
        for (int j = 0; j < 4; j++) {
            int s = tid + j * 256;
            int r = s >> 3, c4 = (s & 7) << 2;
            cpasync16(abuf + (uint32_t)(r * GS + c4) * 4, A + (size_t)(row0 + r) * K + ci * 32 + c4);
            cpasync16(bbuf + (uint32_t)(r * GS + c4) * 4, Bm + (size_t)(col0 + r) * K + ci * 32 + c4);
        }
        asm volatile("cp.async.commit_group;" ::: "memory");
    };

    issue(0, 0);
    if (nchunk > 1) issue(1, 1);

    for (int i = 0; i < nchunk; i++) {
        const int st = i & 1;
        if (i + 1 < nchunk) asm volatile("cp.async.wait_group 1;" ::: "memory");
        else                asm volatile("cp.async.wait_group 0;" ::: "memory");
        __syncthreads();

        const float* As = sm + st * STAGE_FLOATS;
        const float* Bs = As + 128 * GS;
#pragma unroll
        for (int ks = 0; ks < 4; ks++) {
            const int kb = ks * 8;
            uint32_t afr[4][4];
#pragma unroll
            for (int mt = 0; mt < 4; mt++) {
                int r = wm * 64 + mt * 16 + g;
                afr[mt][0] = __float_as_uint(As[r * GS + kb + tig]);
                afr[mt][1] = __float_as_uint(As[(r + 8) * GS + kb + tig]);
                afr[mt][2] = __float_as_uint(As[r * GS + kb + tig + 4]);
                afr[mt][3] = __float_as_uint(As[(r + 8) * GS + kb + tig + 4]);
            }
            uint32_t bfr[4][2];
#pragma unroll
            for (int nt = 0; nt < 4; nt++) {
                int c = wn * 32 + nt * 8 + g;
                bfr[nt][0] = __float_as_uint(Bs[c * GS + kb + tig]);
                bfr[nt][1] = __float_as_uint(Bs[c * GS + kb + tig + 4]);
            }
#pragma unroll
            for (int mt = 0; mt < 4; mt++)
#pragma unroll
                for (int nt = 0; nt < 4; nt++)
                    mma_tf32(acc[mt][nt], afr[mt], bfr[nt]);
        }
        __syncthreads();
        if (i + 2 < nchunk) issue(i + 2, st);
    }

#pragma unroll
    for (int mt = 0; mt < 4; mt++) {
        int r = row0 + wm * 64 + mt * 16 + g;
#pragma unroll
        for (int nt = 0; nt < 4; nt++) {
            int c = col0 + wn * 32 + nt * 8 + tig * 2;
            *(float2*)(C + (size_t)r * N + c)       = make_float2(acc[mt][nt][0], acc[mt][nt][1]);
            *(float2*)(C + (size_t)(r + 8) * N + c) = make_float2(acc[mt][nt][2], acc[mt][nt][3]);
        }
    }
}

// ============ tensor-core flash attention (round-8 proven, kv fused buffer) ============
#define FQ  128
#define FKT 64
#define QS  132
#define PS2 68
#define FLASH2_SMEM ((FQ * QS + 2 * FKT * QS + FQ * PS2) * 4)
#define KVSTR 1024

__global__ void __launch_bounds__(256)
flash_mma(const float* __restrict__ Qb, const float* __restrict__ KVb,
          float* __restrict__ Ob) {
    extern __shared__ float sm[];
    float* Qs = sm;
    float* Ks = sm + FQ * QS;
    float* Vs = Ks + FKT * QS;
    float* Ps = Vs + FKT * QS;
    const int qt = blockIdx.x, h = blockIdx.y, b = blockIdx.z;
    const int kvh = h >> 2;
    const int tid = threadIdx.x, lane = tid & 31, w = tid >> 5;
    const int g = lane >> 2, tig = lane & 3;
    const int q0 = qt * FQ;
    const float qscale = 0.08838834764831843f * 1.4426950408889634f;

    for (int i = tid; i < FQ * 32; i += 256) {
        int r = i >> 5, c4 = (i & 31) << 2;
        float4 qv = *(const float4*)&Qb[((size_t)(b * T_SZ + q0 + r)) * HID + h * HD + c4];
        Qs[r * QS + c4 + 0] = __uint_as_float(f2tf32(qv.x * qscale));
        Qs[r * QS + c4 + 1] = __uint_as_float(f2tf32(qv.y * qscale));
        Qs[r * QS + c4 + 2] = __uint_as_float(f2tf32(qv.z * qscale));
        Qs[r * QS + c4 + 3] = __uint_as_float(f2tf32(qv.w * qscale));
    }

    float O[16][4];
#pragma unroll
    for (int nt = 0; nt < 16; nt++)
#pragma unroll
        for (int j = 0; j < 4; j++) O[nt][j] = 0.f;
    float m0 = -1e30f, m1 = -1e30f, l0 = 0.f, l1 = 0.f;

    const int row_g = q0 + w * 16 + g;
    const int ntile = 2 * qt + 2;

    for (int kt = 0; kt < ntile; kt++) {
        const int k0 = kt * FKT;
        for (int i = tid; i < FKT * 32; i += 256) {
            int r = i >> 5, c4 = (i & 31) << 2;
            size_t base = ((size_t)(b * T_SZ + k0 + r)) * KVSTR + kvh * HD + c4;
            float4 k4 = *(const float4*)&KVb[base];
            Ks[r * QS + c4 + 0] = __uint_as_float(f2tf32(k4.x));
            Ks[r * QS + c4 + 1] = __uint_as_float(f2tf32(k4.y));
            Ks[r * QS + c4 + 2] = __uint_as_float(f2tf32(k4.z));
            Ks[r * QS + c4 + 3] = __uint_as_float(f2tf32(k4.w));
            float4 v4 = *(const float4*)&KVb[base + 512];
            Vs[r * QS + c4 + 0] = __uint_as_float(f2tf32(v4.x));
            Vs[r * QS + c4 + 1] = __uint_as_float(f2tf32(v4.y));
            Vs[r * QS + c4 + 2] = __uint_as_float(f2tf32(v4.z));
            Vs[r * QS + c4 + 3] = __uint_as_float(f2tf32(v4.w));
        }
        __syncthreads();

        float sfr[8][4];
#pragma unroll
        for (int nt = 0; nt < 8; nt++)
#pragma unroll
            for (int j = 0; j < 4; j++) sfr[nt][j] = 0.f;
#pragma unroll
        for (int ks = 0; ks < 16; ks++) {
            const int kb = ks * 8;
            uint32_t a[4];
            int r = w * 16 + g;
            a[0] = __float_as_uint(Qs[r * QS + kb + tig]);
            a[1] = __float_as_uint(Qs[(r + 8) * QS + kb + tig]);
            a[2] = __float_as_uint(Qs[r * QS + kb + tig + 4]);
            a[3] = __float_as_uint(Qs[(r + 8) * QS + kb + tig + 4]);
#pragma unroll
            for (int nt = 0; nt < 8; nt++) {
                uint32_t bb[2];
                bb[0] = __float_as_uint(Ks[(nt * 8 + g) * QS + kb + tig]);
                bb[1] = __float_as_uint(Ks[(nt * 8 + g) * QS + kb + tig + 4]);
                mma_tf32(sfr[nt], a, bb);
            }
        }

        if (k0 + FKT - 1 > q0 + w * 16) {
#pragma unroll
            for (int nt = 0; nt < 8; nt++) {
                int c = k0 + nt * 8 + 2 * tig;
                if (c     > row_g)     sfr[nt][0] = -1e30f;
                if (c + 1 > row_g)     sfr[nt][1] = -1e30f;
                if (c     > row_g + 8) sfr[nt][2] = -1e30f;
                if (c + 1 > row_g + 8) sfr[nt][3] = -1e30f;
            }
        }

        float mx0 = -1e30f, mx1 = -1e30f;
#pragma unroll
        for (int nt = 0; nt < 8; nt++) {
            mx0 = fmaxf(mx0, fmaxf(sfr[nt][0], sfr[nt][1]));
            mx1 = fmaxf(mx1, fmaxf(sfr[nt][2], sfr[nt][3]));
        }
        mx0 = fmaxf(mx0, __shfl_xor_sync(0xffffffffu, mx0, 1));
        mx0 = fmaxf(mx0, __shfl_xor_sync(0xffffffffu, mx0, 2));
        mx1 = fmaxf(mx1, __shfl_xor_sync(0xffffffffu, mx1, 1));
        mx1 = fmaxf(mx1, __shfl_xor_sync(0xffffffffu, mx1, 2));
        float mn0 = fmaxf(m0, mx0), mn1 = fmaxf(m1, mx1);
        float al0 = ex2(m0 - mn0), al1 = ex2(m1 - mn1);
        m0 = mn0; m1 = mn1;

        float ps0 = 0.f, ps1 = 0.f;
        const int pr = (w * 16 + g) * PS2;
#pragma unroll
        for (int nt = 0; nt < 8; nt++) {
            float p0 = ex2(sfr[nt][0] - mn0);
            float p1 = ex2(sfr[nt][1] - mn0);
            float p2 = ex2(sfr[nt][2] - mn1);
            float p3 = ex2(sfr[nt][3] - mn1);
            ps0 += p0 + p1;
            ps1 += p2 + p3;
            int c = nt * 8 + 2 * tig;
            *(float2*)&Ps[pr + c] =
                make_float2(__uint_as_float(f2tf32(p0)), __uint_as_float(f2tf32(p1)));
            *(float2*)&Ps[pr + 8 * PS2 + c] =
                make_float2(__uint_as_float(f2tf32(p2)), __uint_as_float(f2tf32(p3)));
        }
        ps0 += __shfl_xor_sync(0xffffffffu, ps0, 1);
        ps0 += __shfl_xor_sync(0xffffffffu, ps0, 2);
        ps1 += __shfl_xor_sync(0xffffffffu, ps1, 1);
        ps1 += __shfl_xor_sync(0xffffffffu, ps1, 2);
        l0 = l0 * al0 + ps0;
        l1 = l1 * al1 + ps1;
#pragma unroll
        for (int nt = 0; nt < 16; nt++) {
            O[nt][0] *= al0; O[nt][1] *= al0;
            O[nt][2] *= al1; O[nt][3] *= al1;
        }
        __syncwarp();

#pragma unroll
        for (int ks = 0; ks < 8; ks++) {
            const int kb = ks * 8;
            uint32_t a[4];
            int r = w * 16 + g;
            a[0] = __float_as_uint(Ps[r * PS2 + kb + tig]);
            a[1] = __float_as_uint(Ps[(r + 8) * PS2 + kb + tig]);
            a[2] = __float_as_uint(Ps[r * PS2 + kb + tig + 4]);
            a[3] = __float_as_uint(Ps[(r + 8) * PS2 + kb + tig + 4]);
#pragma unroll
            for (int nt = 0; nt < 16; nt++) {
                uint32_t bb[2];
                bb[0] = __float_as_uint(Vs[(kb + tig) * QS + nt * 8 + g]);
                bb[1] = __float_as_uint(Vs[(kb + tig + 4) * QS + nt * 8 + g]);
                mma_tf32(O[nt], a, bb);
            }
        }
        __syncthreads();
    }

    float inv0 = 1.f / l0, inv1 = 1.f / l1;
    size_t r0 = (size_t)(b * T_SZ + row_g) * HID + h * HD;
    size_t r1 = (size_t)(b * T_SZ + row_g + 8) * HID + h * HD;
#pragma unroll
    for (int nt = 0; nt < 16; nt++) {
        int c = nt * 8 + 2 * tig;
        *(float2*)&Ob[r0 + c] = make_float2(O[nt][0] * inv0, O[nt][1] * inv0);
        *(float2*)&Ob[r1 + c] = make_float2(O[nt][2] * inv1, O[nt][3] * inv1);
    }
}

// ---------------- launch ----------------
extern "C" void kernel_launch(void* const* d_in, const int* in_sizes, int n_in,
                              void* d_out, int out_size) {
    const float* x  = (const float*)d_in[0];
    const float* Wq = (const float*)d_in[2];
    const float* Wk = (const float*)d_in[3];
    const float* Wv = (const float*)d_in[4];
    const float* Wo = (const float*)d_in[5];
    float* out = (float*)d_out;

    float *q, *kv, *attn, *xt, *attn_t, *wq_t, *wkv_t, *wo_t;
    cudaGetSymbolAddress((void**)&q, g_q);
    cudaGetSymbolAddress((void**)&kv, g_kv);
    cudaGetSymbolAddress((void**)&attn, g_attn);
    cudaGetSymbolAddress((void**)&xt, g_xt);
    cudaGetSymbolAddress((void**)&attn_t, g_attn_t);
    cudaGetSymbolAddress((void**)&wq_t, g_wq_t);
    cudaGetSymbolAddress((void**)&wkv_t, g_wkv_t);
    cudaGetSymbolAddress((void**)&wo_t, g_wo_t);

    const int M = B_SZ * T_SZ;  // 4096

    cudaFuncSetAttribute(gemm_pipe, cudaFuncAttributeMaxDynamicSharedMemorySize, GEMM_SMEM);
    cudaFuncSetAttribute(flash_mma, cudaFuncAttributeMaxDynamicSharedMemorySize, FLASH2_SMEM);

    // tf32 prepass
    const int XE = M * HID / 4, WQE = HID * HID / 4, WKE = 512 * HID / 4;
    conv_tf32<<<(XE + 255) / 256, 256>>>((const float4*)x, (float4*)xt, XE);
    conv_tf32<<<(WQE + 255) / 256, 256>>>((const float4*)Wq, (float4*)wq_t, WQE);
    conv_tf32<<<(WKE + 255) / 256, 256>>>((const float4*)Wk, (float4*)wkv_t, WKE);
    conv_tf32<<<(WKE + 255) / 256, 256>>>((const float4*)Wv, (float4*)(wkv_t + (size_t)512 * HID), WKE);
    conv_tf32<<<(WQE + 255) / 256, 256>>>((const float4*)Wo, (float4*)wo_t, WQE);

    // projections (pipelined tf32 mma)
    gemm_pipe<<<dim3(HID / 128, M / 128), 256, GEMM_SMEM>>>(xt, wq_t, q, HID, HID);
    gemm_pipe<<<dim3(1024 / 128, M / 128), 256, GEMM_SMEM>>>(xt, wkv_t, kv, 1024, HID);

    // RoPE
    build_rope_table<<<(T_SZ * 64 + 255) / 256, 256>>>();
    rope_kernel<<<(M * NH * 64 + 255) / 256, 256>>>(q, NH, HID);
    rope_kernel<<<(M * NKV * 64 + 255) / 256, 256>>>(kv, NKV, KVSTR);

    // attention
    flash_mma<<<dim3(T_SZ / FQ, NH, B_SZ), 256, FLASH2_SMEM>>>(q, kv, attn);

    // output projection
    conv_tf32<<<(XE + 255) / 256, 256>>>((const float4*)attn, (float4*)attn_t, XE);
    gemm_pipe<<<dim3(HID / 128, M / 128), 256, GEMM_SMEM>>>(attn_t, wo_t, out, HID, HID);
}

// round 10
// speedup vs baseline: 3.4644x; 1.0712x over previous
#include <cuda_runtime.h>
#include <cuda_bf16.h>
#include <math.h>
#include <stdint.h>

#define B_SZ 2
#define T_SZ 2048
#define HID  2048
#define NH   16
#define NKV  4
#define HD   128

// ---------------- scratch ----------------
__device__ float g_q[(size_t)B_SZ * T_SZ * HID];
__device__ float g_kv[(size_t)B_SZ * T_SZ * 1024];        // k: cols 0-511, v: 512-1023
__device__ float g_attn[(size_t)B_SZ * T_SZ * HID];
__device__ float g_xt[(size_t)B_SZ * T_SZ * HID];         // tf32-rounded copies
__device__ float g_wq_t[(size_t)HID * HID];
__device__ float g_wkv_t[(size_t)1024 * HID];
__device__ float g_wo_t[(size_t)HID * HID];
__device__ float g_cos[T_SZ * 64];
__device__ float g_sin[T_SZ * 64];

// ---------------- helpers ----------------
__device__ __forceinline__ uint32_t f2tf32(float f) {
    uint32_t u; asm("cvt.rna.tf32.f32 %0, %1;" : "=r"(u) : "f"(f)); return u;
}
__device__ __forceinline__ void mma_tf32(float* d, const uint32_t* a, const uint32_t* b) {
    asm volatile(
        "mma.sync.aligned.m16n8k8.row.col.f32.tf32.tf32.f32 "
        "{%0,%1,%2,%3}, {%4,%5,%6,%7}, {%8,%9}, {%0,%1,%2,%3};\n"
        : "+f"(d[0]), "+f"(d[1]), "+f"(d[2]), "+f"(d[3])
        : "r"(a[0]), "r"(a[1]), "r"(a[2]), "r"(a[3]), "r"(b[0]), "r"(b[1]));
}
__device__ __forceinline__ float ex2(float x) {
    float y; asm("ex2.approx.ftz.f32 %0, %1;" : "=f"(y) : "f"(x)); return y;
}
__device__ __forceinline__ uint32_t smem_u32(const void* p) {
    uint32_t a;
    asm("{ .reg .u64 t; cvta.to.shared.u64 t, %1; cvt.u32.u64 %0, t; }" : "=r"(a) : "l"(p));
    return a;
}
__device__ __forceinline__ void cpasync16(uint32_t dst, const void* src) {
    asm volatile("cp.async.cg.shared.global [%0], [%1], 16;" :: "r"(dst), "l"(src));
}
__device__ __forceinline__ void cpcommit() {
    asm volatile("cp.async.commit_group;" ::: "memory");
}
template <int N> __device__ __forceinline__ void cpwait() {
    asm volatile("cp.async.wait_group %0;" :: "n"(N) : "memory");
}

// ---------------- tf32 rounding prepass ----------------
__global__ void conv_tf32(const float4* __restrict__ in, float4* __restrict__ out, int n4) {
    int i = blockIdx.x * blockDim.x + threadIdx.x;
    if (i >= n4) return;
    float4 v = in[i];
    out[i] = make_float4(__uint_as_float(f2tf32(v.x)), __uint_as_float(f2tf32(v.y)),
                         __uint_as_float(f2tf32(v.z)), __uint_as_float(f2tf32(v.w)));
}

// ---------------- RoPE ----------------
__global__ void build_rope_table() {
    int idx = blockIdx.x * blockDim.x + threadIdx.x;
    if (idx >= T_SZ * 64) return;
    int i = idx & 63;
    int t = idx >> 6;
    double inv_freq = pow(10000.0, -(double)i / 64.0);
    double ang = (double)t * inv_freq;
    g_cos[idx] = (float)cos(ang);
    g_sin[idx] = (float)sin(ang);
}

// applies rope, then writes round_tf32(val * scale)
__global__ void rope_kernel(float* __restrict__ buf, int nheads, int rowstr, float scale) {
    int idx = blockIdx.x * blockDim.x + threadIdx.x;
    int total = B_SZ * T_SZ * nheads * 64;
    if (idx >= total) return;
    int i  = idx & 63;
    int h  = (idx >> 6) % nheads;
    int bt = idx / (64 * nheads);
    int t  = bt & (T_SZ - 1);
    float c = g_cos[t * 64 + i];
    float s = g_sin[t * 64 + i];
    float* p = buf + (size_t)bt * rowstr + h * HD + i;
    float x1 = p[0], x2 = p[64];
    p[0]  = __uint_as_float(f2tf32((x1 * c - x2 * s) * scale));
    p[64] = __uint_as_float(f2tf32((x2 * c + x1 * s) * scale));
}

// ============ cp.async pipelined tf32 GEMM (round-9 proven) ============
#define GS 36
#define STAGE_FLOATS (2 * 128 * GS)
#define GEMM_SMEM (2 * STAGE_FLOATS * 4)

__global__ void __launch_bounds__(256)
gemm_pipe(const float* __restrict__ A, const float* __restrict__ Bm,
          float* __restrict__ C, int N, int K) {
    extern __shared__ float sm[];
    const uint32_t sbase = smem_u32(sm);
    const int tid  = threadIdx.x;
    const int lane = tid & 31, w = tid >> 5;
    const int wm = w & 1, wn = w >> 1;
    const int g = lane >> 2, tig = lane & 3;
    const int row0 = blockIdx.y * 128, col0 = blockIdx.x * 128;
    const int nchunk = K / 32;

    float acc[4][4][4];
#pragma unroll
    for (int mt = 0; mt < 4; mt++)
#pragma unroll
        for (int nt = 0; nt < 4; nt++)
#pragma unroll
            for (int j = 0; j < 4; j++) acc[mt][nt][j] = 0.f;

    auto issue = [&](int ci, int st) {
        uint32_t abuf = sbase + (uint32_t)st * STAGE_FLOATS * 4;
        uint32_t bbuf = abuf + 128 * GS * 4;
#pragma unroll
        for (int j = 0; j < 4; j++) {
            int s = tid + j * 256;
            int r = s >> 3, c4 = (s & 7) << 2;
            cpasync16(abuf + (uint32_t)(r * GS + c4) * 4, A + (size_t)(row0 + r) * K + ci * 32 + c4);
            cpasync16(bbuf + (uint32_t)(r * GS + c4) * 4, Bm + (size_t)(col0 + r) * K + ci * 32 + c4);
        }
        cpcommit();
    };

    issue(0, 0);
    if (nchunk > 1) issue(1, 1);

    for (int i = 0; i < nchunk; i++) {
        const int st = i & 1;
        if (i + 1 < nchunk) cpwait<1>();
        else                cpwait<0>();
        __syncthreads();

        const float* As = sm + st * STAGE_FLOATS;
        const float* Bs = As + 128 * GS;
#pragma unroll
        for (int ks = 0; ks < 4; ks++) {
            const int kb = ks * 8;
            uint32_t afr[4][4];
#pragma unroll
            for (int mt = 0; mt < 4; mt++) {
                int r = wm * 64 + mt * 16 + g;
                afr[mt][0] = __float_as_uint(As[r * GS + kb + tig]);
                afr[mt][1] = __float_as_uint(As[(r + 8) * GS + kb + tig]);
                afr[mt][2] = __float_as_uint(As[r * GS + kb + tig + 4]);
                afr[mt][3] = __float_as_uint(As[(r + 8) * GS + kb + tig + 4]);
            }
            uint32_t bfr[4][2];
#pragma unroll
            for (int nt = 0; nt < 4; nt++) {
                int c = wn * 32 + nt * 8 + g;
                bfr[nt][0] = __float_as_uint(Bs[c * GS + kb + tig]);
                bfr[nt][1] = __float_as_uint(Bs[c * GS + kb + tig + 4]);
            }
#pragma unroll
            for (int mt = 0; mt < 4; mt++)
#pragma unroll
                for (int nt = 0; nt < 4; nt++)
                    mma_tf32(acc[mt][nt], afr[mt], bfr[nt]);
        }
        __syncthreads();
        if (i + 2 < nchunk) issue(i + 2, st);
    }

#pragma unroll
    for (int mt = 0; mt < 4; mt++) {
        int r = row0 + wm * 64 + mt * 16 + g;
#pragma unroll
        for (int nt = 0; nt < 4; nt++) {
            int c = col0 + wn * 32 + nt * 8 + tig * 2;
            *(float2*)(C + (size_t)r * N + c)       = make_float2(acc[mt][nt][0], acc[mt][nt][1]);
            *(float2*)(C + (size_t)(r + 8) * N + c) = make_float2(acc[mt][nt][2], acc[mt][nt][3]);
        }
    }
}

// ============ cp.async pipelined tensor-core flash attention ============
// Q pre-scaled+rounded; KV pre-rounded. K double-buffered, V early-issued.
#define FQ  128
#define FKT 64
#define QS  132
#define PS2 68
#define KVSTR 1024
// smem floats: Q 128*132 | K stage0/1 64*132 each | V 64*132 | P 128*68
#define F_QOFF 0
#define F_KOFF(st) (128 * QS + (st) * (FKT * QS))
#define F_VOFF (128 * QS + 2 * FKT * QS)
#define F_POFF (F_VOFF + FKT * QS)
#define FLASH3_SMEM ((F_POFF + FQ * PS2) * 4)

__global__ void __launch_bounds__(256)
flash_mma(const float* __restrict__ Qb, const float* __restrict__ KVb,
          float* __restrict__ Ob) {
    extern __shared__ float sm[];
    const uint32_t sbase = smem_u32(sm);
    float* Ps = sm + F_POFF;
    const int qt = blockIdx.x, h = blockIdx.y, b = blockIdx.z;
    const int kvh = h >> 2;
    const int tid = threadIdx.x, lane = tid & 31, w = tid >> 5;
    const int g = lane >> 2, tig = lane & 3;
    const int q0 = qt * FQ;

    const int ntile = 2 * qt + 2;

    // issue K tile kt into stage st
    auto issueK = [&](int kt, int st) {
        uint32_t buf = sbase + (uint32_t)F_KOFF(st) * 4;
#pragma unroll
        for (int j = 0; j < 8; j++) {
            int i = tid + j * 256;
            int r = i >> 5, c4 = (i & 31) << 2;
            cpasync16(buf + (uint32_t)(r * QS + c4) * 4,
                      KVb + (size_t)(b * T_SZ + kt * FKT + r) * KVSTR + kvh * HD + c4);
        }
        cpcommit();
    };
    auto issueV = [&](int kt) {
        uint32_t buf = sbase + (uint32_t)F_VOFF * 4;
#pragma unroll
        for (int j = 0; j < 8; j++) {
            int i = tid + j * 256;
            int r = i >> 5, c4 = (i & 31) << 2;
            cpasync16(buf + (uint32_t)(r * QS + c4) * 4,
                      KVb + (size_t)(b * T_SZ + kt * FKT + r) * KVSTR + kvh * HD + 512 + c4);
        }
        cpcommit();
    };

    issueK(0, 0);

    // load Q tile (pre-scaled+rounded in gmem; plain copy)
    for (int i = tid; i < FQ * 32; i += 256) {
        int r = i >> 5, c4 = (i & 31) << 2;
        *(float4*)&sm[F_QOFF + r * QS + c4] =
            *(const float4*)&Qb[((size_t)(b * T_SZ + q0 + r)) * HID + h * HD + c4];
    }

    float O[16][4];
#pragma unroll
    for (int nt = 0; nt < 16; nt++)
#pragma unroll
        for (int j = 0; j < 4; j++) O[nt][j] = 0.f;
    float m0 = -1e30f, m1 = -1e30f, l0 = 0.f, l1 = 0.f;

    const int row_g = q0 + w * 16 + g;

    for (int kt = 0; kt < ntile; kt++) {
        const int k0 = kt * FKT;
        const bool more = (kt + 1 < ntile);
        issueV(kt);
        if (more) issueK(kt + 1, (kt + 1) & 1);

        // wait K(kt): pending after issues = {K(kt),V(kt)[,K(kt+1)]}
        if (more) cpwait<2>(); else cpwait<1>();
        __syncthreads();

        const float* Ks = sm + F_KOFF(kt & 1);
        const float* Qs = sm + F_QOFF;
        float sfr[8][4];
#pragma unroll
        for (int nt = 0; nt < 8; nt++)
#pragma unroll
            for (int j = 0; j < 4; j++) sfr[nt][j] = 0.f;
#pragma unroll
        for (int ks = 0; ks < 16; ks++) {
            const int kb = ks * 8;
            uint32_t a[4];
            int r = w * 16 + g;
            a[0] = __float_as_uint(Qs[r * QS + kb + tig]);
            a[1] = __float_as_uint(Qs[(r + 8) * QS + kb + tig]);
            a[2] = __float_as_uint(Qs[r * QS + kb + tig + 4]);
            a[3] = __float_as_uint(Qs[(r + 8) * QS + kb + tig + 4]);
#pragma unroll
            for (int nt = 0; nt < 8; nt++) {
                uint32_t bb[2];
                bb[0] = __float_as_uint(Ks[(nt * 8 + g) * QS + kb + tig]);
                bb[1] = __float_as_uint(Ks[(nt * 8 + g) * QS + kb + tig + 4]);
                mma_tf32(sfr[nt], a, bb);
            }
        }

        if (k0 + FKT - 1 > q0 + w * 16) {
#pragma unroll
            for (int nt = 0; nt < 8; nt++) {
                int c = k0 + nt * 8 + 2 * tig;
                if (c     > row_g)     sfr[nt][0] = -1e30f;
                if (c + 1 > row_g)     sfr[nt][1] = -1e30f;
                if (c     > row_g + 8) sfr[nt][2] = -1e30f;
                if (c + 1 > row_g + 8) sfr[nt][3] = -1e30f;
            }
        }

        float mx0 = -1e30f, mx1 = -1e30f;
#pragma unroll
        for (int nt = 0; nt < 8; nt++) {
            mx0 = fmaxf(mx0, fmaxf(sfr[nt][0], sfr[nt][1]));
            mx1 = fmaxf(mx1, fmaxf(sfr[nt][2], sfr[nt][3]));
        }
        mx0 = fmaxf(mx0, __shfl_xor_sync(0xffffffffu, mx0, 1));
        mx0 = fmaxf(mx0, __shfl_xor_sync(0xffffffffu, mx0, 2));
        mx1 = fmaxf(mx1, __shfl_xor_sync(0xffffffffu, mx1, 1));
        mx1 = fmaxf(mx1, __shfl_xor_sync(0xffffffffu, mx1, 2));
        float mn0 = fmaxf(m0, mx0), mn1 = fmaxf(m1, mx1);
        float al0 = ex2(m0 - mn0), al1 = ex2(m1 - mn1);
        m0 = mn0; m1 = mn1;

        // wait V(kt), leave K(kt+1) in flight
        if (more) cpwait<1>(); else cpwait<0>();
        __syncthreads();

        float ps0 = 0.f, ps1 = 0.f;
        const int pr = (w * 16 + g) * PS2;
#pragma unroll
        for (int nt = 0; nt < 8; nt++) {
            float p0 = ex2(sfr[nt][0] - mn0);
            float p1 = ex2(sfr[nt][1] - mn0);
            float p2 = ex2(sfr[nt][2] - mn1);
            float p3 = ex2(sfr[nt][3] - mn1);
            ps0 += p0 + p1;
            ps1 += p2 + p3;
            int c = nt * 8 + 2 * tig;
            *(float2*)&Ps[pr + c] =
                make_float2(__uint_as_float(f2tf32(p0)), __uint_as_float(f2tf32(p1)));
            *(float2*)&Ps[pr + 8 * PS2 + c] =
                make_float2(__uint_as_float(f2tf32(p2)), __uint_as_float(f2tf32(p3)));
        }
        ps0 += __shfl_xor_sync(0xffffffffu, ps0, 1);
        ps0 += __shfl_xor_sync(0xffffffffu, ps0, 2);
        ps1 += __shfl_xor_sync(0xffffffffu, ps1, 1);
        ps1 += __shfl_xor_sync(0xffffffffu, ps1, 2);
        l0 = l0 * al0 + ps0;
        l1 = l1 * al1 + ps1;
#pragma unroll
        for (int nt = 0; nt < 16; nt++) {
            O[nt][0] *= al0; O[nt][1] *= al0;
            O[nt][2] *= al1; O[nt][3] *= al1;
        }
        __syncwarp();

        const float* Vs = sm + F_VOFF;
#pragma unroll
        for (int ks = 0; ks < 8; ks++) {
            const int kb = ks * 8;
            uint32_t a[4];
            int r = w * 16 + g;
            a[0] = __float_as_uint(Ps[r * PS2 + kb + tig]);
            a[1] = __float_as_uint(Ps[(r + 8) * PS2 + kb + tig]);
            a[2] = __float_as_uint(Ps[r * PS2 + kb + tig + 4]);
            a[3] = __float_as_uint(Ps[(r + 8) * PS2 + kb + tig + 4]);
#pragma unroll
            for (int nt = 0; nt < 16; nt++) {
                uint32_t bb[2];
                bb[0] = __float_as_uint(Vs[(kb + tig) * QS + nt * 8 + g]);
                bb[1] = __float_as_uint(Vs[(kb + tig + 4) * QS + nt * 8 + g]);
                mma_tf32(O[nt], a, bb);
            }
        }
        __syncthreads();   // V buffer + P reusable next iter
    }

    // epilogue: write tf32-rounded O (feeds Wo GEMM directly, no conv pass)
    float inv0 = 1.f / l0, inv1 = 1.f / l1;
    size_t r0 = (size_t)(b * T_SZ + row_g) * HID + h * HD;
    size_t r1 = (size_t)(b * T_SZ + row_g + 8) * HID + h * HD;
#pragma unroll
    for (int nt = 0; nt < 16; nt++) {
        int c = nt * 8 + 2 * tig;
        *(float2*)&Ob[r0 + c] = make_float2(__uint_as_float(f2tf32(O[nt][0] * inv0)),
                                            __uint_as_float(f2tf32(O[nt][1] * inv0)));
        *(float2*)&Ob[r1 + c] = make_float2(__uint_as_float(f2tf32(O[nt][2] * inv1)),
                                            __uint_as_float(f2tf32(O[nt][3] * inv1)));
    }
}

// ---------------- launch ----------------
extern "C" void kernel_launch(void* const* d_in, const int* in_sizes, int n_in,
                              void* d_out, int out_size) {
    const float* x  = (const float*)d_in[0];
    const float* Wq = (const float*)d_in[2];
    const float* Wk = (const float*)d_in[3];
    const float* Wv = (const float*)d_in[4];
    const float* Wo = (const float*)d_in[5];
    float* out = (float*)d_out;

    float *q, *kv, *attn, *xt, *wq_t, *wkv_t, *wo_t;
    cudaGetSymbolAddress((void**)&q, g_q);
    cudaGetSymbolAddress((void**)&kv, g_kv);
    cudaGetSymbolAddress((void**)&attn, g_attn);
    cudaGetSymbolAddress((void**)&xt, g_xt);
    cudaGetSymbolAddress((void**)&wq_t, g_wq_t);
    cudaGetSymbolAddress((void**)&wkv_t, g_wkv_t);
    cudaGetSymbolAddress((void**)&wo_t, g_wo_t);

    const int M = B_SZ * T_SZ;  // 4096
    const float qscale = 0.08838834764831843f * 1.4426950408889634f;

    cudaFuncSetAttribute(gemm_pipe, cudaFuncAttributeMaxDynamicSharedMemorySize, GEMM_SMEM);
    cudaFuncSetAttribute(flash_mma, cudaFuncAttributeMaxDynamicSharedMemorySize, FLASH3_SMEM);

    // tf32 prepass
    const int XE = M * HID / 4, WQE = HID * HID / 4, WKE = 512 * HID / 4;
    conv_tf32<<<(XE + 255) / 256, 256>>>((const float4*)x, (float4*)xt, XE);
    conv_tf32<<<(WQE + 255) / 256, 256>>>((const float4*)Wq, (float4*)wq_t, WQE);
    conv_tf32<<<(WKE + 255) / 256, 256>>>((const float4*)Wk, (float4*)wkv_t, WKE);
    conv_tf32<<<(WKE + 255) / 256, 256>>>((const float4*)Wv, (float4*)(wkv_t + (size_t)512 * HID), WKE);
    conv_tf32<<<(WQE + 255) / 256, 256>>>((const float4*)Wo, (float4*)wo_t, WQE);

    // projections
    gemm_pipe<<<dim3(HID / 128, M / 128), 256, GEMM_SMEM>>>(xt, wq_t, q, HID, HID);
    gemm_pipe<<<dim3(1024 / 128, M / 128), 256, GEMM_SMEM>>>(xt, wkv_t, kv, 1024, HID);

    // RoPE (q: fold softmax scale + round; kv K-part: round only)
    build_rope_table<<<(T_SZ * 64 + 255) / 256, 256>>>();
    rope_kernel<<<(M * NH * 64 + 255) / 256, 256>>>(q, NH, HID, qscale);
    rope_kernel<<<(M * NKV * 64 + 255) / 256, 256>>>(kv, NKV, KVSTR, 1.0f);

    // round V (and re-round K, idempotent)
    const int KVE = M * 1024 / 4;
    conv_tf32<<<(KVE + 255) / 256, 256>>>((const float4*)kv, (float4*)kv, KVE);

    // attention (pipelined; writes rounded attn)
    flash_mma<<<dim3(T_SZ / FQ, NH, B_SZ), 256, FLASH3_SMEM>>>(q, kv, attn);

    // output projection
    gemm_pipe<<<dim3(HID / 128, M / 128), 256, GEMM_SMEM>>>(attn, wo_t, out, HID, HID);
}

// round 11
// speedup vs baseline: 7.6834x; 2.2178x over previous
#include <cuda_runtime.h>
#include <cuda_fp16.h>
#include <math.h>
#include <stdint.h>

#define B_SZ 2
#define T_SZ 2048
#define HID  2048
#define NH   16
#define NKV  4
#define HD   128

// ---------------- scratch (half precision intermediates) ----------------
__device__ __half g_q[(size_t)B_SZ * T_SZ * HID];
__device__ __half g_kv[(size_t)B_SZ * T_SZ * 1024];   // k cols 0-511, v 512-1023
__device__ __half g_attn[(size_t)B_SZ * T_SZ * HID];
__device__ __half g_xh[(size_t)B_SZ * T_SZ * HID];
__device__ __half g_wq_h[(size_t)HID * HID];
__device__ __half g_wkv_h[(size_t)1024 * HID];
__device__ __half g_wo_h[(size_t)HID * HID];
__device__ float g_cos[T_SZ * 64];
__device__ float g_sin[T_SZ * 64];

// ---------------- helpers ----------------
__device__ __forceinline__ void mma_f16(float* d, const uint32_t* a, const uint32_t* b) {
    asm volatile(
        "mma.sync.aligned.m16n8k16.row.col.f32.f16.f16.f32 "
        "{%0,%1,%2,%3}, {%4,%5,%6,%7}, {%8,%9}, {%0,%1,%2,%3};\n"
        : "+f"(d[0]), "+f"(d[1]), "+f"(d[2]), "+f"(d[3])
        : "r"(a[0]), "r"(a[1]), "r"(a[2]), "r"(a[3]), "r"(b[0]), "r"(b[1]));
}
__device__ __forceinline__ void ldsm4(uint32_t* r, uint32_t addr) {
    asm volatile("ldmatrix.sync.aligned.m8n8.x4.shared.b16 {%0,%1,%2,%3}, [%4];"
        : "=r"(r[0]), "=r"(r[1]), "=r"(r[2]), "=r"(r[3]) : "r"(addr));
}
__device__ __forceinline__ void ldsm4t(uint32_t* r, uint32_t addr) {
    asm volatile("ldmatrix.sync.aligned.m8n8.x4.trans.shared.b16 {%0,%1,%2,%3}, [%4];"
        : "=r"(r[0]), "=r"(r[1]), "=r"(r[2]), "=r"(r[3]) : "r"(addr));
}
__device__ __forceinline__ float ex2(float x) {
    float y; asm("ex2.approx.ftz.f32 %0, %1;" : "=f"(y) : "f"(x)); return y;
}
__device__ __forceinline__ uint32_t smem_u32(const void* p) {
    uint32_t a;
    asm("{ .reg .u64 t; cvta.to.shared.u64 t, %1; cvt.u32.u64 %0, t; }" : "=r"(a) : "l"(p));
    return a;
}
__device__ __forceinline__ void cpasync16(uint32_t dst, const void* src) {
    asm volatile("cp.async.cg.shared.global [%0], [%1], 16;" :: "r"(dst), "l"(src));
}
__device__ __forceinline__ void cpcommit() {
    asm volatile("cp.async.commit_group;" ::: "memory");
}
template <int N> __device__ __forceinline__ void cpwait() {
    asm volatile("cp.async.wait_group %0;" :: "n"(N) : "memory");
}
__device__ __forceinline__ uint32_t packh2(float a, float b) {
    __half2 h = __floats2half2_rn(a, b);
    return *(uint32_t*)&h;
}

// ---------------- fp32 -> fp16 conversion prepass ----------------
__global__ void conv_half(const float4* __restrict__ in, uint4* __restrict__ out, int n8) {
    int i = blockIdx.x * blockDim.x + threadIdx.x;
    if (i >= n8) return;
    float4 a = in[2 * i], b = in[2 * i + 1];
    uint4 o;
    o.x = packh2(a.x, a.y); o.y = packh2(a.z, a.w);
    o.z = packh2(b.x, b.y); o.w = packh2(b.z, b.w);
    out[i] = o;
}

// ---------------- RoPE ----------------
__global__ void build_rope_table() {
    int idx = blockIdx.x * blockDim.x + threadIdx.x;
    if (idx >= T_SZ * 64) return;
    int i = idx & 63;
    int t = idx >> 6;
    double inv_freq = pow(10000.0, -(double)i / 64.0);
    double ang = (double)t * inv_freq;
    g_cos[idx] = (float)cos(ang);
    g_sin[idx] = (float)sin(ang);
}

__global__ void rope_half(__half* __restrict__ buf, int nheads, int rowstr, float scale) {
    int idx = blockIdx.x * blockDim.x + threadIdx.x;
    int total = B_SZ * T_SZ * nheads * 64;
    if (idx >= total) return;
    int i  = idx & 63;
    int h  = (idx >> 6) % nheads;
    int bt = idx / (64 * nheads);
    int t  = bt & (T_SZ - 1);
    float c = g_cos[t * 64 + i];
    float s = g_sin[t * 64 + i];
    __half* p = buf + (size_t)bt * rowstr + h * HD + i;
    float x1 = __half2float(p[0]), x2 = __half2float(p[64]);
    p[0]  = __float2half_rn((x1 * c - x2 * s) * scale);
    p[64] = __float2half_rn((x2 * c + x1 * s) * scale);
}

// ============ fp16 mma GEMM: C[M,N] = A[M,K]*B[N,K]^T, cp.async 2-stage ============
// Tile 128x128, BK=64 halves. ldmatrix fragment loads.
#define HS 72                       // smem row stride in halves (144B)
#define G_ATILE (128 * HS)          // halves per tile
#define G_STAGE (2 * G_ATILE)
#define GEMM_SMEM (2 * G_STAGE * 2) // bytes

template <bool OUT_HALF>
__global__ void __launch_bounds__(256)
gemm_h(const __half* __restrict__ A, const __half* __restrict__ Bm,
       void* __restrict__ Cout, int N, int K) {
    extern __shared__ __half hsm[];
    const uint32_t sbase = smem_u32(hsm);
    const int tid  = threadIdx.x;
    const int lane = tid & 31, w = tid >> 5;
    const int wm = w & 1, wn = w >> 1;
    const int g = lane >> 2, tig = lane & 3;
    const int row0 = blockIdx.y * 128, col0 = blockIdx.x * 128;
    const int nchunk = K / 64;

    // ldmatrix lane offsets
    const int a_row_l = lane & 15, a_col_l = (lane >> 4) * 8;
    const int b_n_l = ((lane >> 4) & 1) * 8 + (lane & 7);
    const int b_k_l = ((lane >> 3) & 1) * 8;

    float acc[4][4][4];
#pragma unroll
    for (int mt = 0; mt < 4; mt++)
#pragma unroll
        for (int nt = 0; nt < 4; nt++)
#pragma unroll
            for (int j = 0; j < 4; j++) acc[mt][nt][j] = 0.f;

    auto issue = [&](int ci, int st) {
        uint32_t abuf = sbase + (uint32_t)(st * G_STAGE) * 2;
        uint32_t bbuf = abuf + G_ATILE * 2;
#pragma unroll
        for (int j = 0; j < 4; j++) {
            int s = tid + j * 256;
            int r = s >> 3, c8 = (s & 7) << 3;
            cpasync16(abuf + (uint32_t)(r * HS + c8) * 2, A + (size_t)(row0 + r) * K + ci * 64 + c8);
            cpasync16(bbuf + (uint32_t)(r * HS + c8) * 2, Bm + (size_t)(col0 + r) * K + ci * 64 + c8);
        }
        cpcommit();
    };

    issue(0, 0);
    if (nchunk > 1) issue(1, 1);

    for (int i = 0; i < nchunk; i++) {
        const int st = i & 1;
        if (i + 1 < nchunk) cpwait<1>();
        else                cpwait<0>();
        __syncthreads();

        uint32_t abuf = sbase + (uint32_t)(st * G_STAGE) * 2;
        uint32_t bbuf = abuf + G_ATILE * 2;
#pragma unroll
        for (int ks = 0; ks < 4; ks++) {
            uint32_t af[4][4];
#pragma unroll
            for (int mt = 0; mt < 4; mt++)
                ldsm4(af[mt], abuf + (uint32_t)((wm * 64 + mt * 16 + a_row_l) * HS + ks * 16 + a_col_l) * 2);
            uint32_t bf[2][4];
#pragma unroll
            for (int ntp = 0; ntp < 2; ntp++)
                ldsm4(bf[ntp], bbuf + (uint32_t)((wn * 32 + ntp * 16 + b_n_l) * HS + ks * 16 + b_k_l) * 2);
#pragma unroll
            for (int mt = 0; mt < 4; mt++)
#pragma unroll
                for (int nt = 0; nt < 4; nt++)
                    mma_f16(acc[mt][nt], af[mt], &bf[nt >> 1][(nt & 1) * 2]);
        }
        __syncthreads();
        if (i + 2 < nchunk) issue(i + 2, st);
    }

#pragma unroll
    for (int mt = 0; mt < 4; mt++) {
        int r = row0 + wm * 64 + mt * 16 + g;
#pragma unroll
        for (int nt = 0; nt < 4; nt++) {
            int c = col0 + wn * 32 + nt * 8 + tig * 2;
            if (OUT_HALF) {
                __half* C = (__half*)Cout;
                *(uint32_t*)(C + (size_t)r * N + c)       = packh2(acc[mt][nt][0], acc[mt][nt][1]);
                *(uint32_t*)(C + (size_t)(r + 8) * N + c) = packh2(acc[mt][nt][2], acc[mt][nt][3]);
            } else {
                float* C = (float*)Cout;
                *(float2*)(C + (size_t)r * N + c)       = make_float2(acc[mt][nt][0], acc[mt][nt][1]);
                *(float2*)(C + (size_t)(r + 8) * N + c) = make_float2(acc[mt][nt][2], acc[mt][nt][3]);
            }
        }
    }
}

// ============ fp16 flash attention: register P (FA2), ldmatrix, cp.async ============
#define FQ  128
#define FKT 64
#define FHS 136                      // smem row stride halves (272B)
#define FQO 0
#define FKO(st) (128 * FHS + (st) * 64 * FHS)
#define FVO (128 * FHS + 2 * 64 * FHS)
#define FLASH_SMEM_H ((FVO + 64 * FHS) * 2)
#define KVSTR 1024

__global__ void __launch_bounds__(256)
flash_h(const __half* __restrict__ Qb, const __half* __restrict__ KVb,
        __half* __restrict__ Ob) {
    extern __shared__ __half hsm[];
    const uint32_t sbase = smem_u32(hsm);
    const int qt = blockIdx.x, h = blockIdx.y, b = blockIdx.z;
    const int kvh = h >> 2;
    const int tid = threadIdx.x, lane = tid & 31, w = tid >> 5;
    const int g = lane >> 2, tig = lane & 3;
    const int q0 = qt * FQ;
    const int ntile = 2 * qt + 2;

    const int a_row_l = lane & 15, a_col_l = (lane >> 4) * 8;
    const int b_n_l = ((lane >> 4) & 1) * 8 + (lane & 7);
    const int b_k_l = ((lane >> 3) & 1) * 8;
    const int v_row_l = ((lane >> 3) & 1) * 8 + (lane & 7);
    const int v_col_l = (lane >> 4) * 8;

    auto issueK = [&](int kt, int st) {
        uint32_t buf = sbase + (uint32_t)FKO(st) * 2;
#pragma unroll
        for (int j = 0; j < 4; j++) {
            int s = tid + j * 256;
            int r = s >> 4, c8 = (s & 15) << 3;
            cpasync16(buf + (uint32_t)(r * FHS + c8) * 2,
                      KVb + (size_t)(b * T_SZ + kt * FKT + r) * KVSTR + kvh * HD + c8);
        }
        cpcommit();
    };
    auto issueV = [&](int kt) {
        uint32_t buf = sbase + (uint32_t)FVO * 2;
#pragma unroll
        for (int j = 0; j < 4; j++) {
            int s = tid + j * 256;
            int r = s >> 4, c8 = (s & 15) << 3;
            cpasync16(buf + (uint32_t)(r * FHS + c8) * 2,
                      KVb + (size_t)(b * T_SZ + kt * FKT + r) * KVSTR + kvh * HD + 512 + c8);
        }
        cpcommit();
    };

    issueK(0, 0);

    // Q tile copy (pre-scaled+rounded in gmem)
#pragma unroll
    for (int j = 0; j < 8; j++) {
        int s = tid + j * 256;
        int r = s >> 4, c8 = (s & 15) << 3;
        *(uint4*)&hsm[FQO + r * FHS + c8] =
            *(const uint4*)&Qb[((size_t)(b * T_SZ + q0 + r)) * HID + h * HD + c8];
    }

    float O[16][4];
#pragma unroll
    for (int nt = 0; nt < 16; nt++)
#pragma unroll
        for (int j = 0; j < 4; j++) O[nt][j] = 0.f;
    float m0 = -1e30f, m1 = -1e30f, l0 = 0.f, l1 = 0.f;
    const int row_g = q0 + w * 16 + g;

    for (int kt = 0; kt < ntile; kt++) {
        const int k0 = kt * FKT;
        const bool more = (kt + 1 < ntile);
        issueV(kt);
        if (more) issueK(kt + 1, (kt + 1) & 1);
        if (more) cpwait<2>(); else cpwait<1>();
        __syncthreads();

        const uint32_t qbuf = sbase + (uint32_t)FQO * 2;
        const uint32_t kbuf = sbase + (uint32_t)FKO(kt & 1) * 2;

        // S = Q K^T : 8 k-steps x 8 n-tiles
        float sfr[8][4];
#pragma unroll
        for (int nt = 0; nt < 8; nt++)
#pragma unroll
            for (int j = 0; j < 4; j++) sfr[nt][j] = 0.f;
#pragma unroll
        for (int ks = 0; ks < 8; ks++) {
            uint32_t a[4];
            ldsm4(a, qbuf + (uint32_t)((w * 16 + a_row_l) * FHS + ks * 16 + a_col_l) * 2);
#pragma unroll
            for (int ntp = 0; ntp < 4; ntp++) {
                uint32_t bf[4];
                ldsm4(bf, kbuf + (uint32_t)((ntp * 16 + b_n_l) * FHS + ks * 16 + b_k_l) * 2);
                mma_f16(sfr[2 * ntp],     a, &bf[0]);
                mma_f16(sfr[2 * ntp + 1], a, &bf[2]);
            }
        }

        if (k0 + FKT - 1 > q0 + w * 16) {
#pragma unroll
            for (int nt = 0; nt < 8; nt++) {
                int c = k0 + nt * 8 + 2 * tig;
                if (c     > row_g)     sfr[nt][0] = -1e30f;
                if (c + 1 > row_g)     sfr[nt][1] = -1e30f;
                if (c     > row_g + 8) sfr[nt][2] = -1e30f;
                if (c + 1 > row_g + 8) sfr[nt][3] = -1e30f;
            }
        }

        float mx0 = -1e30f, mx1 = -1e30f;
#pragma unroll
        for (int nt = 0; nt < 8; nt++) {
            mx0 = fmaxf(mx0, fmaxf(sfr[nt][0], sfr[nt][1]));
            mx1 = fmaxf(mx1, fmaxf(sfr[nt][2], sfr[nt][3]));
        }
        mx0 = fmaxf(mx0, __shfl_xor_sync(0xffffffffu, mx0, 1));
        mx0 = fmaxf(mx0, __shfl_xor_sync(0xffffffffu, mx0, 2));
        mx1 = fmaxf(mx1, __shfl_xor_sync(0xffffffffu, mx1, 1));
        mx1 = fmaxf(mx1, __shfl_xor_sync(0xffffffffu, mx1, 2));
        float mn0 = fmaxf(m0, mx0), mn1 = fmaxf(m1, mx1);
        float al0 = ex2(m0 - mn0), al1 = ex2(m1 - mn1);
        m0 = mn0; m1 = mn1;

        // P in registers, packed as PV A-fragments (no smem round-trip)
        float ps0 = 0.f, ps1 = 0.f;
        uint32_t pa[4][4];
#pragma unroll
        for (int nt = 0; nt < 8; nt++) {
            float p0 = ex2(sfr[nt][0] - mn0);
            float p1 = ex2(sfr[nt][1] - mn0);
            float p2 = ex2(sfr[nt][2] - mn1);
            float p3 = ex2(sfr[nt][3] - mn1);
            ps0 += p0 + p1;
            ps1 += p2 + p3;
            pa[nt >> 1][(nt & 1) * 2 + 0] = packh2(p0, p1);
            pa[nt >> 1][(nt & 1) * 2 + 1] = packh2(p2, p3);
        }
        ps0 += __shfl_xor_sync(0xffffffffu, ps0, 1);
        ps0 += __shfl_xor_sync(0xffffffffu, ps0, 2);
        ps1 += __shfl_xor_sync(0xffffffffu, ps1, 1);
        ps1 += __shfl_xor_sync(0xffffffffu, ps1, 2);
        l0 = l0 * al0 + ps0;
        l1 = l1 * al1 + ps1;
#pragma unroll
        for (int nt = 0; nt < 16; nt++) {
            O[nt][0] *= al0; O[nt][1] *= al0;
            O[nt][2] *= al1; O[nt][3] *= al1;
        }

        // wait V(kt); K(kt+1) stays in flight
        if (more) cpwait<1>(); else cpwait<0>();
        __syncthreads();

        const uint32_t vbuf = sbase + (uint32_t)FVO * 2;
#pragma unroll
        for (int ks = 0; ks < 4; ks++) {
#pragma unroll
            for (int ntp = 0; ntp < 8; ntp++) {
                uint32_t bf[4];
                ldsm4t(bf, vbuf + (uint32_t)((ks * 16 + v_row_l) * FHS + ntp * 16 + v_col_l) * 2);
                mma_f16(O[2 * ntp],     pa[ks], &bf[0]);
                mma_f16(O[2 * ntp + 1], pa[ks], &bf[2]);
            }
        }
        __syncthreads();
    }

    float inv0 = 1.f / l0, inv1 = 1.f / l1;
    size_t r0 = (size_t)(b * T_SZ + row_g) * HID + h * HD;
    size_t r1 = (size_t)(b * T_SZ + row_g + 8) * HID + h * HD;
#pragma unroll
    for (int nt = 0; nt < 16; nt++) {
        int c = nt * 8 + 2 * tig;
        *(uint32_t*)&Ob[r0 + c] = packh2(O[nt][0] * inv0, O[nt][1] * inv0);
        *(uint32_t*)&Ob[r1 + c] = packh2(O[nt][2] * inv1, O[nt][3] * inv1);
    }
}

// ---------------- launch ----------------
extern "C" void kernel_launch(void* const* d_in, const int* in_sizes, int n_in,
                              void* d_out, int out_size) {
    const float* x  = (const float*)d_in[0];
    const float* Wq = (const float*)d_in[2];
    const float* Wk = (const float*)d_in[3];
    const float* Wv = (const float*)d_in[4];
    const float* Wo = (const float*)d_in[5];
    float* out = (float*)d_out;

    __half *q, *kv, *attn, *xh, *wq_h, *wkv_h, *wo_h;
    cudaGetSymbolAddress((void**)&q, g_q);
    cudaGetSymbolAddress((void**)&kv, g_kv);
    cudaGetSymbolAddress((void**)&attn, g_attn);
    cudaGetSymbolAddress((void**)&xh, g_xh);
    cudaGetSymbolAddress((void**)&wq_h, g_wq_h);
    cudaGetSymbolAddress((void**)&wkv_h, g_wkv_h);
    cudaGetSymbolAddress((void**)&wo_h, g_wo_h);

    const int M = B_SZ * T_SZ;  // 4096
    const float qscale = 0.08838834764831843f * 1.4426950408889634f;

    cudaFuncSetAttribute(gemm_h<true>,  cudaFuncAttributeMaxDynamicSharedMemorySize, GEMM_SMEM);
    cudaFuncSetAttribute(gemm_h<false>, cudaFuncAttributeMaxDynamicSharedMemorySize, GEMM_SMEM);
    cudaFuncSetAttribute(flash_h, cudaFuncAttributeMaxDynamicSharedMemorySize, FLASH_SMEM_H);

    // fp16 prepass
    const int XE = M * HID / 8, WQE = HID * HID / 8, WKE = 512 * HID / 8;
    conv_half<<<(XE + 255) / 256, 256>>>((const float4*)x, (uint4*)xh, XE);
    conv_half<<<(WQE + 255) / 256, 256>>>((const float4*)Wq, (uint4*)wq_h, WQE);
    conv_half<<<(WKE + 255) / 256, 256>>>((const float4*)Wk, (uint4*)wkv_h, WKE);
    conv_half<<<(WKE + 255) / 256, 256>>>((const float4*)Wv, (uint4*)(wkv_h + (size_t)512 * HID), WKE);
    conv_half<<<(WQE + 255) / 256, 256>>>((const float4*)Wo, (uint4*)wo_h, WQE);

    // projections (fp16 mma, half outputs)
    gemm_h<true><<<dim3(HID / 128, M / 128), 256, GEMM_SMEM>>>(xh, wq_h, q, HID, HID);
    gemm_h<true><<<dim3(1024 / 128, M / 128), 256, GEMM_SMEM>>>(xh, wkv_h, kv, 1024, HID);

    // RoPE (q: folds softmax*log2e scale; k: plain)
    build_rope_table<<<(T_SZ * 64 + 255) / 256, 256>>>();
    rope_half<<<(M * NH * 64 + 255) / 256, 256>>>(q, NH, HID, qscale);
    rope_half<<<(M * NKV * 64 + 255) / 256, 256>>>(kv, NKV, KVSTR, 1.0f);

    // attention
    flash_h<<<dim3(T_SZ / FQ, NH, B_SZ), 256, FLASH_SMEM_H>>>(q, kv, attn);

    // output projection (float out)
    gemm_h<false><<<dim3(HID / 128, M / 128), 256, GEMM_SMEM>>>(attn, wo_h, out, HID, HID);
}